// round 13
// baseline (speedup 1.0000x reference)
#include <cuda_runtime.h>
#include <cuda_bf16.h>
#include <math.h>
#include <stdint.h>

#define H 128
#define KN 20
#define NB 65536
#define NEGV (-1e9f)

// ---------------- device scratch ----------------
__device__ float g_A[129 * 128];
__device__ float g_C[129 * 128];
__device__ float g_bp[128];
__device__ float g_z[2u * NB * 128];                 // zu | zv
__device__ unsigned short g_Whi[128 * 512];          // W1^T hi (bf16 bits) [n][k]
__device__ unsigned short g_Wlo[128 * 512];          // W1^T lo

__device__ __forceinline__ void cp16(void* smem, const void* gmem) {
    const uint32_t s = (uint32_t)__cvta_generic_to_shared(smem);
    asm volatile("cp.async.cg.shared.global [%0], [%1], 16;"
                 :: "r"(s), "l"(__cvta_generic_to_global(gmem)) : "memory");
}
#define CP_COMMIT() asm volatile("cp.async.commit_group;" ::: "memory")
#define CP_WAIT0()  asm volatile("cp.async.wait_group 0;" ::: "memory")

// packed bf16x2 convert: d.lo = x, d.hi = y  (round-to-nearest, same as _rn)
__device__ __forceinline__ uint32_t cvt_bf16x2(float x, float y) {
    uint32_t r;
    asm("cvt.rn.bf16x2.f32 %0, %1, %2;" : "=r"(r) : "f"(y), "f"(x));
    return r;
}

// =========================================================================
// Kernel 1 (merged): blocks 0..128 -> piecewise-linear decomposition;
// blocks 129..192 -> W1 transpose + bf16 hi/lo split.
// =========================================================================
__global__ void __launch_bounds__(512) prolog_kernel(
    const float* __restrict__ tp_w1, const float* __restrict__ tp_b1,
    const float* __restrict__ tp_w2, const float* __restrict__ tp_b2,
    const float* __restrict__ em_w1)
{
    const int tid = threadIdx.x;

    if (blockIdx.x < 129) {
        __shared__ float sw[128], sb[128], sbp[128];
        __shared__ int   srank[128];
        __shared__ float pa[3][128], pc[3][128];

        if (tid < 128) {
            const float w = tp_w1[tid], b = tp_b1[tid];
            const float bp = (w != 0.0f) ? (-b / w) : INFINITY;
            sw[tid] = w; sb[tid] = b; sbp[tid] = bp;
        }
        __syncthreads();
        if (tid < 128) {
            const float bp = sbp[tid];
            int r = 0;
            #pragma unroll 8
            for (int j = 0; j < 128; j++) {
                const float bj = sbp[j];
                if (bj < bp || (bj == bp && j < tid)) r++;
            }
            srank[tid] = r;
            if (blockIdx.x == 0) g_bp[r] = bp;
        }
        __syncthreads();

        const int s = blockIdx.x;
        const int d = tid & 127;
        const int q = tid >> 7;
        float a = 0.0f, c = 0.0f;
        #pragma unroll 8
        for (int jj = 0; jj < 32; jj++) {
            const int j = q * 32 + jj;
            const float wj = sw[j];
            bool active;
            if (wj > 0.0f)      active = (srank[j] < s);
            else if (wj < 0.0f) active = (srank[j] >= s);
            else                active = (sb[j] > 0.0f);
            if (active) {
                const float w2v = __ldg(&tp_w2[j * 128 + d]);
                a = fmaf(wj, w2v, a);
                c = fmaf(sb[j], w2v, c);
            }
        }
        if (q) { pa[q - 1][d] = a; pc[q - 1][d] = c; }
        __syncthreads();
        if (q == 0) {
            g_A[s * 128 + d] = a + pa[0][d] + pa[1][d] + pa[2][d];
            g_C[s * 128 + d] = c + pc[0][d] + pc[1][d] + pc[2][d] + tp_b2[d];
        }
    } else {
        __shared__ float s[32][33];
        const int blk = blockIdx.x - 129;
        const int bx = blk & 15;          // k-tile (512/32)
        const int by = blk >> 4;          // n-tile (128/32)
        if (tid < 256) {
            const int c = tid & 31;
            const int r8 = tid >> 5;
            #pragma unroll
            for (int p = 0; p < 4; p++) {
                const int r = r8 + p * 8;
                s[r][c] = em_w1[(bx * 32 + r) * 128 + by * 32 + c];
            }
        }
        __syncthreads();
        if (tid < 256) {
            const int c = tid & 31;
            const int r8 = tid >> 5;
            #pragma unroll
            for (int p = 0; p < 4; p++) {
                const int r = r8 + p * 8;
                const int n = by * 32 + r;
                const float v = s[c][r];
                const __nv_bfloat16 hb = __float2bfloat16_rn(v);
                const float rres = v - __bfloat162float(hb);
                const __nv_bfloat16 lb = __float2bfloat16_rn(rres);
                g_Whi[n * 512 + bx * 32 + c] = __bfloat16_as_ushort(hb);
                g_Wlo[n * 512 + bx * 32 + c] = __bfloat16_as_ushort(lb);
            }
        }
    }
}

// =========================================================================
// Kernel 2: temporal attention encoder with validity compaction + fast
// breakpoint range check + register-cached seg-128 A/C rows (hot case).
// =========================================================================
__global__ void __launch_bounds__(256, 3) encode_kernel(
    const int*   __restrict__ edge_index,
    const int*   __restrict__ ets,
    const int*   __restrict__ hnb,
    const int*   __restrict__ hts,
    const int*   __restrict__ hsg,
    const float* __restrict__ nemb,
    const float* __restrict__ semb)
{
    __shared__ float sbp[128];
    if (threadIdx.x < 128) sbp[threadIdx.x] = g_bp[threadIdx.x];
    __syncthreads();

    const int w    = threadIdx.x >> 5;
    const int lane = threadIdx.x & 31;
    const int task = blockIdx.x * 8 + w;
    const int e    = task >> 1;
    const int side = task & 1;

    const int node = edge_index[side * NB + e];
    const int qt   = ets[e];
    const float qtf = (float)qt;

    const float4* nemb4 = (const float4*)nemb;
    const float4* A4 = (const float4*)g_A;
    const float4* C4 = (const float4*)g_C;

    const float4 q4 = __ldg(&nemb4[node * 32 + lane]);
    const float4 s0 = __ldg(&((const float4*)semb)[lane]);
    const float4 s1 = __ldg(&((const float4*)semb)[32 + lane]);
    const float bpmin = sbp[0];
    const float bpmax = sbp[127];

    // hot A/C rows: valid neighbors have delta >= 1, almost always seg == 128
    const float4 a128 = A4[128 * 32 + lane];
    const float4 c128 = C4[128 * 32 + lane];

    unsigned mt_l = 0;
    float    dl_l = 0.0f;
    bool     val_l = false;
    if (lane < KN) {
        const int nb = hnb[node * KN + lane];
        const int ht = hts[node * KN + lane];
        const int sg = hsg[node * KN + lane];
        const float delta = qtf - (float)ht;
        int seg;
        if (delta > bpmax) {
            seg = 128;
        } else if (delta <= bpmin) {
            seg = 0;
        } else {
            int lo = 0, hi = 128;
            #pragma unroll
            for (int it = 0; it < 7; it++) {
                const int mid = (lo + hi) >> 1;
                if (sbp[mid] < delta) lo = mid + 1; else hi = mid;
            }
            seg = lo;
        }
        val_l = (nb != -1) && (ht < qt);
        const unsigned nbc = (nb == -1) ? 0u : (unsigned)nb;
        mt_l = nbc | ((unsigned)seg << 17) | ((unsigned)sg << 25)
                   | (val_l ? (1u << 26) : 0u);
        dl_l = delta;
    }

    unsigned vmask = __ballot_sync(0xffffffffu, val_l);
    if (vmask == 0u) vmask = 0xFFFFFu;
    const int nv = __popc(vmask);
    const int idx = (lane < nv) ? lane : (nv - 1);
    const int pos = __fns(vmask, 0, idx + 1);
    unsigned cmt = __shfl_sync(0xffffffffu, mt_l, pos);
    const float cdl = __shfl_sync(0xffffffffu, dl_l, pos);
    if (lane >= nv) cmt &= ~(1u << 26);
    const int ngroups = (nv + 3) >> 2;

    const float rsH = 0.08838834764831845f;
    float m = -INFINITY;
    float ssum = 0.0f;
    float4 acc = make_float4(0.f, 0.f, 0.f, 0.f);

    unsigned mt[4]; float dl[4]; float4 em[4];
    #pragma unroll
    for (int i = 0; i < 4; i++) {
        mt[i] = __shfl_sync(0xffffffffu, cmt, i);
        dl[i] = __shfl_sync(0xffffffffu, cdl, i);
        em[i] = __ldg(&nemb4[(mt[i] & 0x1FFFFu) * 32 + lane]);
    }

    for (int g = 0; g < ngroups; g++) {
        unsigned mtn[4]; float dln[4]; float4 emn[4];
        const bool more = (g + 1 < ngroups);
        if (more) {
            #pragma unroll
            for (int i = 0; i < 4; i++) {
                const int j = (g + 1) * 4 + i;
                mtn[i] = __shfl_sync(0xffffffffu, cmt, j);
                dln[i] = __shfl_sync(0xffffffffu, cdl, j);
                emn[i] = __ldg(&nemb4[(mtn[i] & 0x1FFFFu) * 32 + lane]);
            }
        }

        float4 kv[4]; float dp[4];
        #pragma unroll
        for (int i = 0; i < 4; i++) {
            const int seg = (mt[i] >> 17) & 0xFF;
            const float4 sg4 = (mt[i] & (1u << 25)) ? s1 : s0;
            float4 a4, c4;
            if (seg == 128) {               // warp-uniform hot path (~99.9%)
                a4 = a128; c4 = c128;
            } else {
                a4 = A4[seg * 32 + lane];
                c4 = C4[seg * 32 + lane];
            }
            kv[i].x = em[i].x + sg4.x + fmaf(a4.x, dl[i], c4.x);
            kv[i].y = em[i].y + sg4.y + fmaf(a4.y, dl[i], c4.y);
            kv[i].z = em[i].z + sg4.z + fmaf(a4.z, dl[i], c4.z);
            kv[i].w = em[i].w + sg4.w + fmaf(a4.w, dl[i], c4.w);
            dp[i] = fmaf(kv[i].x, q4.x, fmaf(kv[i].y, q4.y,
                    fmaf(kv[i].z, q4.z, kv[i].w * q4.w)));
        }

        const float r0 = dp[0] + __shfl_xor_sync(0xffffffffu, dp[0], 16);
        const float r1 = dp[1] + __shfl_xor_sync(0xffffffffu, dp[1], 16);
        const float r2 = dp[2] + __shfl_xor_sync(0xffffffffu, dp[2], 16);
        const float r3 = dp[3] + __shfl_xor_sync(0xffffffffu, dp[3], 16);
        const float m01 = (lane & 16) ? r1 : r0;
        const float m23 = (lane & 16) ? r3 : r2;
        const float q01 = m01 + __shfl_xor_sync(0xffffffffu, m01, 8);
        const float q23 = m23 + __shfl_xor_sync(0xffffffffu, m23, 8);
        float mm = (lane & 8) ? q23 : q01;
        mm += __shfl_xor_sync(0xffffffffu, mm, 4);
        mm += __shfl_xor_sync(0xffffffffu, mm, 2);
        mm += __shfl_xor_sync(0xffffffffu, mm, 1);
        const float t0 = __shfl_sync(0xffffffffu, mm, 0);
        const float t1 = __shfl_sync(0xffffffffu, mm, 16);
        const float t2 = __shfl_sync(0xffffffffu, mm, 8);
        const float t3 = __shfl_sync(0xffffffffu, mm, 24);

        const float sc0 = (mt[0] & (1u << 26)) ? t0 * rsH : NEGV;
        const float sc1 = (mt[1] & (1u << 26)) ? t1 * rsH : NEGV;
        const float sc2 = (mt[2] & (1u << 26)) ? t2 * rsH : NEGV;
        const float sc3 = (mt[3] & (1u << 26)) ? t3 * rsH : NEGV;

        const float mn = fmaxf(m, fmaxf(fmaxf(sc0, sc1), fmaxf(sc2, sc3)));
        const float f  = __expf(m - mn);
        const float w0 = __expf(sc0 - mn);
        const float w1 = __expf(sc1 - mn);
        const float w2 = __expf(sc2 - mn);
        const float w3 = __expf(sc3 - mn);
        ssum = fmaf(ssum, f, w0 + w1 + w2 + w3);
        acc.x = fmaf(w3, kv[3].x, fmaf(w2, kv[2].x, fmaf(w1, kv[1].x, fmaf(w0, kv[0].x, acc.x * f))));
        acc.y = fmaf(w3, kv[3].y, fmaf(w2, kv[2].y, fmaf(w1, kv[1].y, fmaf(w0, kv[0].y, acc.y * f))));
        acc.z = fmaf(w3, kv[3].z, fmaf(w2, kv[2].z, fmaf(w1, kv[1].z, fmaf(w0, kv[0].z, acc.z * f))));
        acc.w = fmaf(w3, kv[3].w, fmaf(w2, kv[2].w, fmaf(w1, kv[1].w, fmaf(w0, kv[0].w, acc.w * f))));
        m = mn;

        if (more) {
            #pragma unroll
            for (int i = 0; i < 4; i++) { mt[i] = mtn[i]; dl[i] = dln[i]; em[i] = emn[i]; }
        }
    }

    const float inv = 1.0f / ssum;
    acc.x *= inv; acc.y *= inv; acc.z *= inv; acc.w *= inv;
    ((float4*)g_z)[(unsigned)(side * NB + e) * 32 + lane] = acc;
}

// =========================================================================
// Kernel 3: split-bf16 mma.sync GEMM MLP, 2 blocks/SM, ldmatrix fragments,
// packed bf16x2 conversion in A staging.  (unchanged from round 12)
// =========================================================================
#define MMA_BF16(C, A, B0, B1) \
    asm volatile("mma.sync.aligned.m16n8k16.row.col.f32.bf16.bf16.f32 " \
        "{%0,%1,%2,%3}, {%4,%5,%6,%7}, {%8,%9}, {%0,%1,%2,%3};" \
        : "+f"((C)[0]), "+f"((C)[1]), "+f"((C)[2]), "+f"((C)[3]) \
        : "r"((A)[0]), "r"((A)[1]), "r"((A)[2]), "r"((A)[3]), "r"(B0), "r"(B1))

#define LDSM_X4(R, addr) \
    asm volatile("ldmatrix.sync.aligned.m8n8.x4.shared.b16 {%0,%1,%2,%3}, [%4];" \
        : "=r"((R)[0]), "=r"((R)[1]), "=r"((R)[2]), "=r"((R)[3]) : "r"(addr))

#define REGION_SZ 18432           // 128 rows x 144 B
#define BUF_SZ    (4 * REGION_SZ) // Ahi, Alo, Bhi, Blo = 73728

extern __shared__ char dsm[];
__global__ void __launch_bounds__(256, 2) mlp_mma_kernel(
    const float* __restrict__ b1,
    const float* __restrict__ w2,
    const float* __restrict__ b2,
    float*       __restrict__ out)
{
    __shared__ float slog[128];

    const int tid  = threadIdx.x;
    const int wid  = tid >> 5;
    const int lane = tid & 31;
    const int e0   = blockIdx.x * 128;

    char* sAhi = dsm;
    char* sAlo = dsm + REGION_SZ;
    char* sBhi = dsm + 2 * REGION_SZ;
    char* sBlo = dsm + 3 * REGION_SZ;

    if (tid < 128) slog[tid] = 0.0f;

    const int wm = wid >> 1;
    const int wn = wid & 1;
    const int g  = lane >> 2;
    const int t2 = (lane & 3) * 2;

    const uint32_t uAhi = (uint32_t)__cvta_generic_to_shared(sAhi);
    const uint32_t uAlo = uAhi + REGION_SZ;
    const uint32_t uBhi = uAhi + 2 * REGION_SZ;
    const uint32_t uBlo = uAhi + 3 * REGION_SZ;
    const int lm = lane >> 3;
    const int lr = lane & 7;
    const uint32_t aofs = (uint32_t)(((lm & 1) * 8 + lr) * 144 + (lm >> 1) * 16);
    const uint32_t bofs = (uint32_t)(((lm >> 1) * 8 + lr) * 144 + (lm & 1) * 16);
    const uint32_t aRow0 = (uint32_t)((wm * 32) * 144);
    const uint32_t aRow1 = (uint32_t)((wm * 32 + 16) * 144);
    const uint32_t bBase = (uint32_t)((wn * 64) * 144);

    float acc[2][8][4];
    #pragma unroll
    for (int mt = 0; mt < 2; mt++)
        #pragma unroll
        for (int nt = 0; nt < 8; nt++)
            #pragma unroll
            for (int u = 0; u < 4; u++)
                acc[mt][nt][u] = 0.0f;

    const int f4 = tid & 15;
    const int r0 = tid >> 4;
    const int bn = tid >> 1;
    const int bhk = tid & 1;

    for (int chunk = 0; chunk < 8; chunk++) {
        const int region = chunk >> 1;
        const int cb4 = (chunk & 1) * 16;
        __syncthreads();

        #pragma unroll
        for (int i = 0; i < 4; i++) {
            const int kk = chunk * 64 + bhk * 32 + i * 8;
            const int so = bn * 144 + (bhk * 32 + i * 8) * 2;
            cp16(sBhi + so, &g_Whi[bn * 512 + kk]);
            cp16(sBlo + so, &g_Wlo[bn * 512 + kk]);
        }
        CP_COMMIT();

        #pragma unroll
        for (int p = 0; p < 8; p++) {
            const int r = r0 + p * 16;
            float4 v;
            if (region == 0) {
                v = ((const float4*)g_z)[(unsigned)(e0 + r) * 32 + cb4 + f4];
            } else if (region == 1) {
                v = ((const float4*)g_z)[(unsigned)(NB + e0 + r) * 32 + cb4 + f4];
            } else {
                const float4 a = ((const float4*)g_z)[(unsigned)(e0 + r) * 32 + cb4 + f4];
                const float4 b = ((const float4*)g_z)[(unsigned)(NB + e0 + r) * 32 + cb4 + f4];
                if (region == 2) {
                    v.x = fabsf(a.x - b.x); v.y = fabsf(a.y - b.y);
                    v.z = fabsf(a.z - b.z); v.w = fabsf(a.w - b.w);
                } else {
                    v.x = a.x * b.x; v.y = a.y * b.y;
                    v.z = a.z * b.z; v.w = a.w * b.w;
                }
            }
            uint2 hv, lv;
            hv.x = cvt_bf16x2(v.x, v.y);
            hv.y = cvt_bf16x2(v.z, v.w);
            const float hxf = __uint_as_float(hv.x << 16);
            const float hyf = __uint_as_float(hv.x & 0xFFFF0000u);
            const float hzf = __uint_as_float(hv.y << 16);
            const float hwf = __uint_as_float(hv.y & 0xFFFF0000u);
            lv.x = cvt_bf16x2(v.x - hxf, v.y - hyf);
            lv.y = cvt_bf16x2(v.z - hzf, v.w - hwf);
            *(uint2*)(sAhi + r * 144 + f4 * 8) = hv;
            *(uint2*)(sAlo + r * 144 + f4 * 8) = lv;
        }
        CP_WAIT0();
        __syncthreads();

        #pragma unroll
        for (int ks = 0; ks < 4; ks++) {
            const uint32_t kof = (uint32_t)(ks * 32);
            uint32_t ah[2][4], al[2][4];
            LDSM_X4(ah[0], uAhi + aRow0 + aofs + kof);
            LDSM_X4(ah[1], uAhi + aRow1 + aofs + kof);
            LDSM_X4(al[0], uAlo + aRow0 + aofs + kof);
            LDSM_X4(al[1], uAlo + aRow1 + aofs + kof);

            uint32_t bh0[8], bh1[8], bl0[8], bl1[8];
            #pragma unroll
            for (int p = 0; p < 4; p++) {
                uint32_t rh[4], rl[4];
                LDSM_X4(rh, uBhi + bBase + (uint32_t)(p * 16 * 144) + bofs + kof);
                LDSM_X4(rl, uBlo + bBase + (uint32_t)(p * 16 * 144) + bofs + kof);
                bh0[2 * p] = rh[0]; bh1[2 * p] = rh[1];
                bh0[2 * p + 1] = rh[2]; bh1[2 * p + 1] = rh[3];
                bl0[2 * p] = rl[0]; bl1[2 * p] = rl[1];
                bl0[2 * p + 1] = rl[2]; bl1[2 * p + 1] = rl[3];
            }

            #pragma unroll
            for (int nt = 0; nt < 8; nt++) {
                #pragma unroll
                for (int mt = 0; mt < 2; mt++) {
                    MMA_BF16(acc[mt][nt], ah[mt], bh0[nt], bh1[nt]);
                    MMA_BF16(acc[mt][nt], ah[mt], bl0[nt], bl1[nt]);
                    MMA_BF16(acc[mt][nt], al[mt], bh0[nt], bh1[nt]);
                }
            }
        }
    }
    __syncthreads();

    float b1v[16], w2v[16];
    #pragma unroll
    for (int nt = 0; nt < 8; nt++) {
        const int n = wn * 64 + nt * 8 + t2;
        b1v[nt * 2]     = __ldg(&b1[n]);
        b1v[nt * 2 + 1] = __ldg(&b1[n + 1]);
        w2v[nt * 2]     = __ldg(&w2[n]);
        w2v[nt * 2 + 1] = __ldg(&w2[n + 1]);
    }
    #pragma unroll
    for (int mt = 0; mt < 2; mt++) {
        float p1 = 0.0f, p2 = 0.0f;
        #pragma unroll
        for (int nt = 0; nt < 8; nt++) {
            p1 += fmaxf(acc[mt][nt][0] + b1v[2 * nt],     0.0f) * w2v[2 * nt]
                + fmaxf(acc[mt][nt][1] + b1v[2 * nt + 1], 0.0f) * w2v[2 * nt + 1];
            p2 += fmaxf(acc[mt][nt][2] + b1v[2 * nt],     0.0f) * w2v[2 * nt]
                + fmaxf(acc[mt][nt][3] + b1v[2 * nt + 1], 0.0f) * w2v[2 * nt + 1];
        }
        const int r1 = wm * 32 + mt * 16 + g;
        atomicAdd(&slog[r1], p1);
        atomicAdd(&slog[r1 + 8], p2);
    }
    __syncthreads();
    if (tid < 128) out[e0 + tid] = slog[tid] + b2[0];
}

// =========================================================================
extern "C" void kernel_launch(void* const* d_in, const int* in_sizes, int n_in,
                              void* d_out, int out_size)
{
    const int*   edge_index = (const int*)  d_in[0];
    const int*   ets        = (const int*)  d_in[1];
    const int*   hnb        = (const int*)  d_in[2];
    const int*   hts        = (const int*)  d_in[3];
    const int*   hsg        = (const int*)  d_in[4];
    const float* nemb       = (const float*)d_in[5];
    const float* semb       = (const float*)d_in[6];
    const float* tp_w1      = (const float*)d_in[7];
    const float* tp_b1      = (const float*)d_in[8];
    const float* tp_w2      = (const float*)d_in[9];
    const float* tp_b2      = (const float*)d_in[10];
    const float* em_w1      = (const float*)d_in[11];
    const float* em_b1      = (const float*)d_in[12];
    const float* em_w2      = (const float*)d_in[13];
    const float* em_b2      = (const float*)d_in[14];
    float* out = (float*)d_out;

    cudaFuncSetAttribute(mlp_mma_kernel,
                         cudaFuncAttributeMaxDynamicSharedMemorySize, BUF_SZ);

    prolog_kernel<<<193, 512>>>(tp_w1, tp_b1, tp_w2, tp_b2, em_w1);
    encode_kernel<<<(2 * NB) / 8, 256>>>(edge_index, ets, hnb, hts, hsg, nemb, semb);
    mlp_mma_kernel<<<NB / 128, 256, BUF_SZ>>>(em_b1, em_w2, em_b2, out);
}

// round 14
// speedup vs baseline: 1.2331x; 1.2331x over previous
#include <cuda_runtime.h>
#include <cuda_bf16.h>
#include <math.h>
#include <stdint.h>

#define H 128
#define KN 20
#define NB 65536
#define NEGV (-1e9f)

// ---------------- device scratch ----------------
__device__ float g_A[129 * 128];
__device__ float g_C[129 * 128];
__device__ float g_bp[128];
__device__ float g_z[2u * NB * 128];                 // zu | zv
__device__ unsigned short g_Whi[128 * 512];          // W1^T hi (bf16 bits) [n][k]
__device__ unsigned short g_Wlo[128 * 512];          // W1^T lo

__device__ __forceinline__ void cp16(void* smem, const void* gmem) {
    const uint32_t s = (uint32_t)__cvta_generic_to_shared(smem);
    asm volatile("cp.async.cg.shared.global [%0], [%1], 16;"
                 :: "r"(s), "l"(__cvta_generic_to_global(gmem)) : "memory");
}
#define CP_COMMIT() asm volatile("cp.async.commit_group;" ::: "memory")
#define CP_WAIT0()  asm volatile("cp.async.wait_group 0;" ::: "memory")

__device__ __forceinline__ uint32_t cvt_bf16x2(float x, float y) {
    uint32_t r;
    asm("cvt.rn.bf16x2.f32 %0, %1, %2;" : "=r"(r) : "f"(y), "f"(x));
    return r;
}

__device__ __forceinline__ float dot4(float4 a, float4 b) {
    return fmaf(a.x, b.x, fmaf(a.y, b.y, fmaf(a.z, b.z, a.w * b.w)));
}

// merged 4-way butterfly: reduces 4 independent values across the warp,
// broadcasts the 4 totals to all lanes.
__device__ __forceinline__ void reduce4(int lane, float d0, float d1, float d2, float d3,
                                        float& t0, float& t1, float& t2, float& t3)
{
    const float r0 = d0 + __shfl_xor_sync(0xffffffffu, d0, 16);
    const float r1 = d1 + __shfl_xor_sync(0xffffffffu, d1, 16);
    const float r2 = d2 + __shfl_xor_sync(0xffffffffu, d2, 16);
    const float r3 = d3 + __shfl_xor_sync(0xffffffffu, d3, 16);
    const float m01 = (lane & 16) ? r1 : r0;
    const float m23 = (lane & 16) ? r3 : r2;
    const float q01 = m01 + __shfl_xor_sync(0xffffffffu, m01, 8);
    const float q23 = m23 + __shfl_xor_sync(0xffffffffu, m23, 8);
    float mm = (lane & 8) ? q23 : q01;
    mm += __shfl_xor_sync(0xffffffffu, mm, 4);
    mm += __shfl_xor_sync(0xffffffffu, mm, 2);
    mm += __shfl_xor_sync(0xffffffffu, mm, 1);
    t0 = __shfl_sync(0xffffffffu, mm, 0);
    t1 = __shfl_sync(0xffffffffu, mm, 16);
    t2 = __shfl_sync(0xffffffffu, mm, 8);
    t3 = __shfl_sync(0xffffffffu, mm, 24);
}

// =========================================================================
// Kernel 1 (merged): blocks 0..128 -> piecewise-linear decomposition;
// blocks 129..192 -> W1 transpose + bf16 hi/lo split.
// =========================================================================
__global__ void __launch_bounds__(512) prolog_kernel(
    const float* __restrict__ tp_w1, const float* __restrict__ tp_b1,
    const float* __restrict__ tp_w2, const float* __restrict__ tp_b2,
    const float* __restrict__ em_w1)
{
    const int tid = threadIdx.x;

    if (blockIdx.x < 129) {
        __shared__ float sw[128], sb[128], sbp[128];
        __shared__ int   srank[128];
        __shared__ float pa[3][128], pc[3][128];

        if (tid < 128) {
            const float w = tp_w1[tid], b = tp_b1[tid];
            const float bp = (w != 0.0f) ? (-b / w) : INFINITY;
            sw[tid] = w; sb[tid] = b; sbp[tid] = bp;
        }
        __syncthreads();
        if (tid < 128) {
            const float bp = sbp[tid];
            int r = 0;
            #pragma unroll 8
            for (int j = 0; j < 128; j++) {
                const float bj = sbp[j];
                if (bj < bp || (bj == bp && j < tid)) r++;
            }
            srank[tid] = r;
            if (blockIdx.x == 0) g_bp[r] = bp;
        }
        __syncthreads();

        const int s = blockIdx.x;
        const int d = tid & 127;
        const int q = tid >> 7;
        float a = 0.0f, c = 0.0f;
        #pragma unroll 8
        for (int jj = 0; jj < 32; jj++) {
            const int j = q * 32 + jj;
            const float wj = sw[j];
            bool active;
            if (wj > 0.0f)      active = (srank[j] < s);
            else if (wj < 0.0f) active = (srank[j] >= s);
            else                active = (sb[j] > 0.0f);
            if (active) {
                const float w2v = __ldg(&tp_w2[j * 128 + d]);
                a = fmaf(wj, w2v, a);
                c = fmaf(sb[j], w2v, c);
            }
        }
        if (q) { pa[q - 1][d] = a; pc[q - 1][d] = c; }
        __syncthreads();
        if (q == 0) {
            g_A[s * 128 + d] = a + pa[0][d] + pa[1][d] + pa[2][d];
            g_C[s * 128 + d] = c + pc[0][d] + pc[1][d] + pc[2][d] + tp_b2[d];
        }
    } else {
        __shared__ float s[32][33];
        const int blk = blockIdx.x - 129;
        const int bx = blk & 15;
        const int by = blk >> 4;
        if (tid < 256) {
            const int c = tid & 31;
            const int r8 = tid >> 5;
            #pragma unroll
            for (int p = 0; p < 4; p++) {
                const int r = r8 + p * 8;
                s[r][c] = em_w1[(bx * 32 + r) * 128 + by * 32 + c];
            }
        }
        __syncthreads();
        if (tid < 256) {
            const int c = tid & 31;
            const int r8 = tid >> 5;
            #pragma unroll
            for (int p = 0; p < 4; p++) {
                const int r = r8 + p * 8;
                const int n = by * 32 + r;
                const float v = s[c][r];
                const __nv_bfloat16 hb = __float2bfloat16_rn(v);
                const float rres = v - __bfloat162float(hb);
                const __nv_bfloat16 lb = __float2bfloat16_rn(rres);
                g_Whi[n * 512 + bx * 32 + c] = __bfloat16_as_ushort(hb);
                g_Wlo[n * 512 + bx * 32 + c] = __bfloat16_as_ushort(lb);
            }
        }
    }
}

// =========================================================================
// Kernel 2: temporal attention encoder. Validity compaction; per-TASK
// fast/slow split: if every contributing lane has seg==128 (~99.9%), the
// time/sign terms fold into 4 per-task scalars and the inner loop touches
// only the em gather.
// =========================================================================
__global__ void __launch_bounds__(256, 3) encode_kernel(
    const int*   __restrict__ edge_index,
    const int*   __restrict__ ets,
    const int*   __restrict__ hnb,
    const int*   __restrict__ hts,
    const int*   __restrict__ hsg,
    const float* __restrict__ nemb,
    const float* __restrict__ semb)
{
    __shared__ float sbp[128];
    if (threadIdx.x < 128) sbp[threadIdx.x] = g_bp[threadIdx.x];
    __syncthreads();

    const int w    = threadIdx.x >> 5;
    const int lane = threadIdx.x & 31;
    const int task = blockIdx.x * 8 + w;
    const int e    = task >> 1;
    const int side = task & 1;

    const int node = edge_index[side * NB + e];
    const int qt   = ets[e];
    const float qtf = (float)qt;

    const float4* nemb4 = (const float4*)nemb;
    const float4* A4 = (const float4*)g_A;
    const float4* C4 = (const float4*)g_C;

    const float4 q4 = __ldg(&nemb4[node * 32 + lane]);
    const float bpmin = sbp[0];
    const float bpmax = sbp[127];

    unsigned mt_l = 0;          // nb(17b) | seg(8b)<<17 | sg<<25 | valid<<26
    float    dl_l = 0.0f;
    bool     val_l = false;
    int      seg_l = 0;
    if (lane < KN) {
        const int nb = hnb[node * KN + lane];
        const int ht = hts[node * KN + lane];
        const int sg = hsg[node * KN + lane];
        const float delta = qtf - (float)ht;
        if (delta > bpmax) {
            seg_l = 128;
        } else if (delta <= bpmin) {
            seg_l = 0;
        } else {
            int lo = 0, hi = 128;
            #pragma unroll
            for (int it = 0; it < 7; it++) {
                const int mid = (lo + hi) >> 1;
                if (sbp[mid] < delta) lo = mid + 1; else hi = mid;
            }
            seg_l = lo;
        }
        val_l = (nb != -1) && (ht < qt);
        const unsigned nbc = (nb == -1) ? 0u : (unsigned)nb;
        mt_l = nbc | ((unsigned)seg_l << 17) | ((unsigned)sg << 25)
                   | (val_l ? (1u << 26) : 0u);
        dl_l = delta;
    }

    const unsigned vball = __ballot_sync(0xffffffffu, val_l);
    const unsigned sball = __ballot_sync(0xffffffffu, (lane < KN) && (seg_l == 128));
    const unsigned contrib = vball ? vball : 0xFFFFFu;
    const bool fast = ((contrib & ~sball) == 0u);

    const int nv = __popc(contrib);
    const int idx = (lane < nv) ? lane : (nv - 1);
    const int pos = __fns(contrib, 0, idx + 1);
    unsigned cmt = __shfl_sync(0xffffffffu, mt_l, pos);
    const float cdl = __shfl_sync(0xffffffffu, dl_l, pos);
    if (lane >= nv) cmt &= ~(1u << 26);
    const int ngroups = (nv + 3) >> 2;

    const float rsH = 0.08838834764831845f;
    float m = -INFINITY;
    float ssum = 0.0f;

    // ---- shared prologue: prefetch group 0 ----
    unsigned mt[4]; float dl[4]; float4 em[4];
    #pragma unroll
    for (int i = 0; i < 4; i++) {
        mt[i] = __shfl_sync(0xffffffffu, cmt, i);
        dl[i] = __shfl_sync(0xffffffffu, cdl, i);
        em[i] = __ldg(&nemb4[(mt[i] & 0x1FFFFu) * 32 + lane]);
    }

    float4 outv;

    if (fast) {
        // per-task scalars: qa=q.A128, qc=q.C128, qs0/qs1=q.sign_emb
        float qa, qc, qs0, qs1;
        {
            const float4 a128 = __ldg(&A4[128 * 32 + lane]);
            const float4 c128 = __ldg(&C4[128 * 32 + lane]);
            const float4 se0 = __ldg(&((const float4*)semb)[lane]);
            const float4 se1 = __ldg(&((const float4*)semb)[32 + lane]);
            reduce4(lane, dot4(a128, q4), dot4(c128, q4),
                    dot4(se0, q4), dot4(se1, q4), qa, qc, qs0, qs1);
        }

        float wd = 0.0f, ws0 = 0.0f;
        float4 acc = make_float4(0.f, 0.f, 0.f, 0.f);

        for (int g = 0; g < ngroups; g++) {
            unsigned mtn[4]; float dln[4]; float4 emn[4];
            const bool more = (g + 1 < ngroups);
            if (more) {
                #pragma unroll
                for (int i = 0; i < 4; i++) {
                    const int j = (g + 1) * 4 + i;
                    mtn[i] = __shfl_sync(0xffffffffu, cmt, j);
                    dln[i] = __shfl_sync(0xffffffffu, cdl, j);
                    emn[i] = __ldg(&nemb4[(mtn[i] & 0x1FFFFu) * 32 + lane]);
                }
            }

            float t0, t1, t2, t3;
            reduce4(lane, dot4(em[0], q4), dot4(em[1], q4),
                    dot4(em[2], q4), dot4(em[3], q4), t0, t1, t2, t3);

            const float a0 = fmaf(qa, dl[0], qc) + ((mt[0] & (1u << 25)) ? qs1 : qs0);
            const float a1 = fmaf(qa, dl[1], qc) + ((mt[1] & (1u << 25)) ? qs1 : qs0);
            const float a2 = fmaf(qa, dl[2], qc) + ((mt[2] & (1u << 25)) ? qs1 : qs0);
            const float a3 = fmaf(qa, dl[3], qc) + ((mt[3] & (1u << 25)) ? qs1 : qs0);

            const float sc0 = (mt[0] & (1u << 26)) ? (t0 + a0) * rsH : NEGV;
            const float sc1 = (mt[1] & (1u << 26)) ? (t1 + a1) * rsH : NEGV;
            const float sc2 = (mt[2] & (1u << 26)) ? (t2 + a2) * rsH : NEGV;
            const float sc3 = (mt[3] & (1u << 26)) ? (t3 + a3) * rsH : NEGV;

            const float mn = fmaxf(m, fmaxf(fmaxf(sc0, sc1), fmaxf(sc2, sc3)));
            const float f  = __expf(m - mn);
            const float w0 = __expf(sc0 - mn);
            const float w1 = __expf(sc1 - mn);
            const float w2 = __expf(sc2 - mn);
            const float w3 = __expf(sc3 - mn);
            ssum = fmaf(ssum, f, w0 + w1 + w2 + w3);
            wd = fmaf(wd, f, fmaf(w0, dl[0], fmaf(w1, dl[1],
                        fmaf(w2, dl[2], w3 * dl[3]))));
            ws0 = fmaf(ws0, f,
                  ((mt[0] & (1u << 25)) ? 0.0f : w0) +
                  ((mt[1] & (1u << 25)) ? 0.0f : w1) +
                  ((mt[2] & (1u << 25)) ? 0.0f : w2) +
                  ((mt[3] & (1u << 25)) ? 0.0f : w3));
            acc.x = fmaf(w3, em[3].x, fmaf(w2, em[2].x, fmaf(w1, em[1].x, fmaf(w0, em[0].x, acc.x * f))));
            acc.y = fmaf(w3, em[3].y, fmaf(w2, em[2].y, fmaf(w1, em[1].y, fmaf(w0, em[0].y, acc.y * f))));
            acc.z = fmaf(w3, em[3].z, fmaf(w2, em[2].z, fmaf(w1, em[1].z, fmaf(w0, em[0].z, acc.z * f))));
            acc.w = fmaf(w3, em[3].w, fmaf(w2, em[2].w, fmaf(w1, em[1].w, fmaf(w0, em[0].w, acc.w * f))));
            m = mn;

            if (more) {
                #pragma unroll
                for (int i = 0; i < 4; i++) { mt[i] = mtn[i]; dl[i] = dln[i]; em[i] = emn[i]; }
            }
        }

        const float inv = 1.0f / ssum;
        const float f0 = ws0 * inv;
        const float f1 = (ssum - ws0) * inv;
        const float wdn = wd * inv;
        const float4 a128 = __ldg(&A4[128 * 32 + lane]);
        const float4 c128 = __ldg(&C4[128 * 32 + lane]);
        const float4 se0 = __ldg(&((const float4*)semb)[lane]);
        const float4 se1 = __ldg(&((const float4*)semb)[32 + lane]);
        outv.x = fmaf(acc.x, inv, fmaf(a128.x, wdn, fmaf(se0.x, f0, fmaf(se1.x, f1, c128.x))));
        outv.y = fmaf(acc.y, inv, fmaf(a128.y, wdn, fmaf(se0.y, f0, fmaf(se1.y, f1, c128.y))));
        outv.z = fmaf(acc.z, inv, fmaf(a128.z, wdn, fmaf(se0.z, f0, fmaf(se1.z, f1, c128.z))));
        outv.w = fmaf(acc.w, inv, fmaf(a128.w, wdn, fmaf(se0.w, f0, fmaf(se1.w, f1, c128.w))));
    } else {
        // ---- general path (rare): full per-k key construction ----
        const float4 se0 = __ldg(&((const float4*)semb)[lane]);
        const float4 se1 = __ldg(&((const float4*)semb)[32 + lane]);
        float4 acc = make_float4(0.f, 0.f, 0.f, 0.f);

        for (int g = 0; g < ngroups; g++) {
            unsigned mtn[4]; float dln[4]; float4 emn[4];
            const bool more = (g + 1 < ngroups);
            if (more) {
                #pragma unroll
                for (int i = 0; i < 4; i++) {
                    const int j = (g + 1) * 4 + i;
                    mtn[i] = __shfl_sync(0xffffffffu, cmt, j);
                    dln[i] = __shfl_sync(0xffffffffu, cdl, j);
                    emn[i] = __ldg(&nemb4[(mtn[i] & 0x1FFFFu) * 32 + lane]);
                }
            }

            float4 kv[4]; float dp[4];
            #pragma unroll
            for (int i = 0; i < 4; i++) {
                const int seg = (mt[i] >> 17) & 0xFF;
                const float4 sg4 = (mt[i] & (1u << 25)) ? se1 : se0;
                const float4 a4 = A4[seg * 32 + lane];
                const float4 c4 = C4[seg * 32 + lane];
                kv[i].x = em[i].x + sg4.x + fmaf(a4.x, dl[i], c4.x);
                kv[i].y = em[i].y + sg4.y + fmaf(a4.y, dl[i], c4.y);
                kv[i].z = em[i].z + sg4.z + fmaf(a4.z, dl[i], c4.z);
                kv[i].w = em[i].w + sg4.w + fmaf(a4.w, dl[i], c4.w);
                dp[i] = dot4(kv[i], q4);
            }

            float t0, t1, t2, t3;
            reduce4(lane, dp[0], dp[1], dp[2], dp[3], t0, t1, t2, t3);

            const float sc0 = (mt[0] & (1u << 26)) ? t0 * rsH : NEGV;
            const float sc1 = (mt[1] & (1u << 26)) ? t1 * rsH : NEGV;
            const float sc2 = (mt[2] & (1u << 26)) ? t2 * rsH : NEGV;
            const float sc3 = (mt[3] & (1u << 26)) ? t3 * rsH : NEGV;

            const float mn = fmaxf(m, fmaxf(fmaxf(sc0, sc1), fmaxf(sc2, sc3)));
            const float f  = __expf(m - mn);
            const float w0 = __expf(sc0 - mn);
            const float w1 = __expf(sc1 - mn);
            const float w2 = __expf(sc2 - mn);
            const float w3 = __expf(sc3 - mn);
            ssum = fmaf(ssum, f, w0 + w1 + w2 + w3);
            acc.x = fmaf(w3, kv[3].x, fmaf(w2, kv[2].x, fmaf(w1, kv[1].x, fmaf(w0, kv[0].x, acc.x * f))));
            acc.y = fmaf(w3, kv[3].y, fmaf(w2, kv[2].y, fmaf(w1, kv[1].y, fmaf(w0, kv[0].y, acc.y * f))));
            acc.z = fmaf(w3, kv[3].z, fmaf(w2, kv[2].z, fmaf(w1, kv[1].z, fmaf(w0, kv[0].z, acc.z * f))));
            acc.w = fmaf(w3, kv[3].w, fmaf(w2, kv[2].w, fmaf(w1, kv[1].w, fmaf(w0, kv[0].w, acc.w * f))));
            m = mn;

            if (more) {
                #pragma unroll
                for (int i = 0; i < 4; i++) { mt[i] = mtn[i]; dl[i] = dln[i]; em[i] = emn[i]; }
            }
        }

        const float inv = 1.0f / ssum;
        outv.x = acc.x * inv; outv.y = acc.y * inv;
        outv.z = acc.z * inv; outv.w = acc.w * inv;
    }

    ((float4*)g_z)[(unsigned)(side * NB + e) * 32 + lane] = outv;
}

// =========================================================================
// Kernel 3: split-bf16 mma.sync GEMM MLP, 2 blocks/SM, ldmatrix fragments,
// packed bf16x2 conversion in A staging.  (unchanged)
// =========================================================================
#define MMA_BF16(C, A, B0, B1) \
    asm volatile("mma.sync.aligned.m16n8k16.row.col.f32.bf16.bf16.f32 " \
        "{%0,%1,%2,%3}, {%4,%5,%6,%7}, {%8,%9}, {%0,%1,%2,%3};" \
        : "+f"((C)[0]), "+f"((C)[1]), "+f"((C)[2]), "+f"((C)[3]) \
        : "r"((A)[0]), "r"((A)[1]), "r"((A)[2]), "r"((A)[3]), "r"(B0), "r"(B1))

#define LDSM_X4(R, addr) \
    asm volatile("ldmatrix.sync.aligned.m8n8.x4.shared.b16 {%0,%1,%2,%3}, [%4];" \
        : "=r"((R)[0]), "=r"((R)[1]), "=r"((R)[2]), "=r"((R)[3]) : "r"(addr))

#define REGION_SZ 18432
#define BUF_SZ    (4 * REGION_SZ)

extern __shared__ char dsm[];
__global__ void __launch_bounds__(256, 2) mlp_mma_kernel(
    const float* __restrict__ b1,
    const float* __restrict__ w2,
    const float* __restrict__ b2,
    float*       __restrict__ out)
{
    __shared__ float slog[128];

    const int tid  = threadIdx.x;
    const int wid  = tid >> 5;
    const int lane = tid & 31;
    const int e0   = blockIdx.x * 128;

    char* sAhi = dsm;
    char* sAlo = dsm + REGION_SZ;
    char* sBhi = dsm + 2 * REGION_SZ;
    char* sBlo = dsm + 3 * REGION_SZ;

    if (tid < 128) slog[tid] = 0.0f;

    const int wm = wid >> 1;
    const int wn = wid & 1;
    const int g  = lane >> 2;
    const int t2 = (lane & 3) * 2;

    const uint32_t uAhi = (uint32_t)__cvta_generic_to_shared(sAhi);
    const uint32_t uAlo = uAhi + REGION_SZ;
    const uint32_t uBhi = uAhi + 2 * REGION_SZ;
    const uint32_t uBlo = uAhi + 3 * REGION_SZ;
    const int lm = lane >> 3;
    const int lr = lane & 7;
    const uint32_t aofs = (uint32_t)(((lm & 1) * 8 + lr) * 144 + (lm >> 1) * 16);
    const uint32_t bofs = (uint32_t)(((lm >> 1) * 8 + lr) * 144 + (lm & 1) * 16);
    const uint32_t aRow0 = (uint32_t)((wm * 32) * 144);
    const uint32_t aRow1 = (uint32_t)((wm * 32 + 16) * 144);
    const uint32_t bBase = (uint32_t)((wn * 64) * 144);

    float acc[2][8][4];
    #pragma unroll
    for (int mt = 0; mt < 2; mt++)
        #pragma unroll
        for (int nt = 0; nt < 8; nt++)
            #pragma unroll
            for (int u = 0; u < 4; u++)
                acc[mt][nt][u] = 0.0f;

    const int f4 = tid & 15;
    const int r0 = tid >> 4;
    const int bn = tid >> 1;
    const int bhk = tid & 1;

    for (int chunk = 0; chunk < 8; chunk++) {
        const int region = chunk >> 1;
        const int cb4 = (chunk & 1) * 16;
        __syncthreads();

        #pragma unroll
        for (int i = 0; i < 4; i++) {
            const int kk = chunk * 64 + bhk * 32 + i * 8;
            const int so = bn * 144 + (bhk * 32 + i * 8) * 2;
            cp16(sBhi + so, &g_Whi[bn * 512 + kk]);
            cp16(sBlo + so, &g_Wlo[bn * 512 + kk]);
        }
        CP_COMMIT();

        #pragma unroll
        for (int p = 0; p < 8; p++) {
            const int r = r0 + p * 16;
            float4 v;
            if (region == 0) {
                v = ((const float4*)g_z)[(unsigned)(e0 + r) * 32 + cb4 + f4];
            } else if (region == 1) {
                v = ((const float4*)g_z)[(unsigned)(NB + e0 + r) * 32 + cb4 + f4];
            } else {
                const float4 a = ((const float4*)g_z)[(unsigned)(e0 + r) * 32 + cb4 + f4];
                const float4 b = ((const float4*)g_z)[(unsigned)(NB + e0 + r) * 32 + cb4 + f4];
                if (region == 2) {
                    v.x = fabsf(a.x - b.x); v.y = fabsf(a.y - b.y);
                    v.z = fabsf(a.z - b.z); v.w = fabsf(a.w - b.w);
                } else {
                    v.x = a.x * b.x; v.y = a.y * b.y;
                    v.z = a.z * b.z; v.w = a.w * b.w;
                }
            }
            uint2 hv, lv;
            hv.x = cvt_bf16x2(v.x, v.y);
            hv.y = cvt_bf16x2(v.z, v.w);
            const float hxf = __uint_as_float(hv.x << 16);
            const float hyf = __uint_as_float(hv.x & 0xFFFF0000u);
            const float hzf = __uint_as_float(hv.y << 16);
            const float hwf = __uint_as_float(hv.y & 0xFFFF0000u);
            lv.x = cvt_bf16x2(v.x - hxf, v.y - hyf);
            lv.y = cvt_bf16x2(v.z - hzf, v.w - hwf);
            *(uint2*)(sAhi + r * 144 + f4 * 8) = hv;
            *(uint2*)(sAlo + r * 144 + f4 * 8) = lv;
        }
        CP_WAIT0();
        __syncthreads();

        #pragma unroll
        for (int ks = 0; ks < 4; ks++) {
            const uint32_t kof = (uint32_t)(ks * 32);
            uint32_t ah[2][4], al[2][4];
            LDSM_X4(ah[0], uAhi + aRow0 + aofs + kof);
            LDSM_X4(ah[1], uAhi + aRow1 + aofs + kof);
            LDSM_X4(al[0], uAlo + aRow0 + aofs + kof);
            LDSM_X4(al[1], uAlo + aRow1 + aofs + kof);

            uint32_t bh0[8], bh1[8], bl0[8], bl1[8];
            #pragma unroll
            for (int p = 0; p < 4; p++) {
                uint32_t rh[4], rl[4];
                LDSM_X4(rh, uBhi + bBase + (uint32_t)(p * 16 * 144) + bofs + kof);
                LDSM_X4(rl, uBlo + bBase + (uint32_t)(p * 16 * 144) + bofs + kof);
                bh0[2 * p] = rh[0]; bh1[2 * p] = rh[1];
                bh0[2 * p + 1] = rh[2]; bh1[2 * p + 1] = rh[3];
                bl0[2 * p] = rl[0]; bl1[2 * p] = rl[1];
                bl0[2 * p + 1] = rl[2]; bl1[2 * p + 1] = rl[3];
            }

            #pragma unroll
            for (int nt = 0; nt < 8; nt++) {
                #pragma unroll
                for (int mt = 0; mt < 2; mt++) {
                    MMA_BF16(acc[mt][nt], ah[mt], bh0[nt], bh1[nt]);
                    MMA_BF16(acc[mt][nt], ah[mt], bl0[nt], bl1[nt]);
                    MMA_BF16(acc[mt][nt], al[mt], bh0[nt], bh1[nt]);
                }
            }
        }
    }
    __syncthreads();

    float b1v[16], w2v[16];
    #pragma unroll
    for (int nt = 0; nt < 8; nt++) {
        const int n = wn * 64 + nt * 8 + t2;
        b1v[nt * 2]     = __ldg(&b1[n]);
        b1v[nt * 2 + 1] = __ldg(&b1[n + 1]);
        w2v[nt * 2]     = __ldg(&w2[n]);
        w2v[nt * 2 + 1] = __ldg(&w2[n + 1]);
    }
    #pragma unroll
    for (int mt = 0; mt < 2; mt++) {
        float p1 = 0.0f, p2 = 0.0f;
        #pragma unroll
        for (int nt = 0; nt < 8; nt++) {
            p1 += fmaxf(acc[mt][nt][0] + b1v[2 * nt],     0.0f) * w2v[2 * nt]
                + fmaxf(acc[mt][nt][1] + b1v[2 * nt + 1], 0.0f) * w2v[2 * nt + 1];
            p2 += fmaxf(acc[mt][nt][2] + b1v[2 * nt],     0.0f) * w2v[2 * nt]
                + fmaxf(acc[mt][nt][3] + b1v[2 * nt + 1], 0.0f) * w2v[2 * nt + 1];
        }
        const int r1 = wm * 32 + mt * 16 + g;
        atomicAdd(&slog[r1], p1);
        atomicAdd(&slog[r1 + 8], p2);
    }
    __syncthreads();
    if (tid < 128) out[e0 + tid] = slog[tid] + b2[0];
}

// =========================================================================
extern "C" void kernel_launch(void* const* d_in, const int* in_sizes, int n_in,
                              void* d_out, int out_size)
{
    const int*   edge_index = (const int*)  d_in[0];
    const int*   ets        = (const int*)  d_in[1];
    const int*   hnb        = (const int*)  d_in[2];
    const int*   hts        = (const int*)  d_in[3];
    const int*   hsg        = (const int*)  d_in[4];
    const float* nemb       = (const float*)d_in[5];
    const float* semb       = (const float*)d_in[6];
    const float* tp_w1      = (const float*)d_in[7];
    const float* tp_b1      = (const float*)d_in[8];
    const float* tp_w2      = (const float*)d_in[9];
    const float* tp_b2      = (const float*)d_in[10];
    const float* em_w1      = (const float*)d_in[11];
    const float* em_b1      = (const float*)d_in[12];
    const float* em_w2      = (const float*)d_in[13];
    const float* em_b2      = (const float*)d_in[14];
    float* out = (float*)d_out;

    cudaFuncSetAttribute(mlp_mma_kernel,
                         cudaFuncAttributeMaxDynamicSharedMemorySize, BUF_SZ);

    prolog_kernel<<<193, 512>>>(tp_w1, tp_b1, tp_w2, tp_b2, em_w1);
    encode_kernel<<<(2 * NB) / 8, 256>>>(edge_index, ets, hnb, hts, hsg, nemb, semb);
    mlp_mma_kernel<<<NB / 128, 256, BUF_SZ>>>(em_b1, em_w2, em_b2, out);
}

// round 15
// speedup vs baseline: 1.2951x; 1.0503x over previous
#include <cuda_runtime.h>
#include <cuda_bf16.h>
#include <math.h>
#include <stdint.h>

#define H 128
#define KN 20
#define NB 65536
#define NEGV (-1e9f)

// ---------------- device scratch ----------------
__device__ float g_A[129 * 128];
__device__ float g_C[129 * 128];
__device__ float g_bp[128];
__device__ float g_z[2u * NB * 128];                 // zu | zv
__device__ unsigned short g_Whi[128 * 512];          // W1^T hi (bf16 bits) [n][k]
__device__ unsigned short g_Wlo[128 * 512];          // W1^T lo

__device__ __forceinline__ void cp16(void* smem, const void* gmem) {
    const uint32_t s = (uint32_t)__cvta_generic_to_shared(smem);
    asm volatile("cp.async.cg.shared.global [%0], [%1], 16;"
                 :: "r"(s), "l"(__cvta_generic_to_global(gmem)) : "memory");
}
#define CP_COMMIT() asm volatile("cp.async.commit_group;" ::: "memory")
#define CP_WAIT0()  asm volatile("cp.async.wait_group 0;" ::: "memory")

__device__ __forceinline__ uint32_t cvt_bf16x2(float x, float y) {
    uint32_t r;
    asm("cvt.rn.bf16x2.f32 %0, %1, %2;" : "=r"(r) : "f"(y), "f"(x));
    return r;
}

__device__ __forceinline__ float dot4(float4 a, float4 b) {
    return fmaf(a.x, b.x, fmaf(a.y, b.y, fmaf(a.z, b.z, a.w * b.w)));
}

// merged 4-way butterfly: reduces 4 independent values, broadcasts totals.
__device__ __forceinline__ void reduce4(int lane, float d0, float d1, float d2, float d3,
                                        float& t0, float& t1, float& t2, float& t3)
{
    const float r0 = d0 + __shfl_xor_sync(0xffffffffu, d0, 16);
    const float r1 = d1 + __shfl_xor_sync(0xffffffffu, d1, 16);
    const float r2 = d2 + __shfl_xor_sync(0xffffffffu, d2, 16);
    const float r3 = d3 + __shfl_xor_sync(0xffffffffu, d3, 16);
    const float m01 = (lane & 16) ? r1 : r0;
    const float m23 = (lane & 16) ? r3 : r2;
    const float q01 = m01 + __shfl_xor_sync(0xffffffffu, m01, 8);
    const float q23 = m23 + __shfl_xor_sync(0xffffffffu, m23, 8);
    float mm = (lane & 8) ? q23 : q01;
    mm += __shfl_xor_sync(0xffffffffu, mm, 4);
    mm += __shfl_xor_sync(0xffffffffu, mm, 2);
    mm += __shfl_xor_sync(0xffffffffu, mm, 1);
    t0 = __shfl_sync(0xffffffffu, mm, 0);
    t1 = __shfl_sync(0xffffffffu, mm, 16);
    t2 = __shfl_sync(0xffffffffu, mm, 8);
    t3 = __shfl_sync(0xffffffffu, mm, 24);
}

// =========================================================================
// Kernel 1 (merged): blocks 0..128 -> piecewise-linear decomposition;
// blocks 129..192 -> W1 transpose + bf16 hi/lo split.
// =========================================================================
__global__ void __launch_bounds__(512) prolog_kernel(
    const float* __restrict__ tp_w1, const float* __restrict__ tp_b1,
    const float* __restrict__ tp_w2, const float* __restrict__ tp_b2,
    const float* __restrict__ em_w1)
{
    const int tid = threadIdx.x;

    if (blockIdx.x < 129) {
        __shared__ float sw[128], sb[128], sbp[128];
        __shared__ int   srank[128];
        __shared__ float pa[3][128], pc[3][128];

        if (tid < 128) {
            const float w = tp_w1[tid], b = tp_b1[tid];
            const float bp = (w != 0.0f) ? (-b / w) : INFINITY;
            sw[tid] = w; sb[tid] = b; sbp[tid] = bp;
        }
        __syncthreads();
        if (tid < 128) {
            const float bp = sbp[tid];
            int r = 0;
            #pragma unroll 8
            for (int j = 0; j < 128; j++) {
                const float bj = sbp[j];
                if (bj < bp || (bj == bp && j < tid)) r++;
            }
            srank[tid] = r;
            if (blockIdx.x == 0) g_bp[r] = bp;
        }
        __syncthreads();

        const int s = blockIdx.x;
        const int d = tid & 127;
        const int q = tid >> 7;
        float a = 0.0f, c = 0.0f;
        #pragma unroll 8
        for (int jj = 0; jj < 32; jj++) {
            const int j = q * 32 + jj;
            const float wj = sw[j];
            bool active;
            if (wj > 0.0f)      active = (srank[j] < s);
            else if (wj < 0.0f) active = (srank[j] >= s);
            else                active = (sb[j] > 0.0f);
            if (active) {
                const float w2v = __ldg(&tp_w2[j * 128 + d]);
                a = fmaf(wj, w2v, a);
                c = fmaf(sb[j], w2v, c);
            }
        }
        if (q) { pa[q - 1][d] = a; pc[q - 1][d] = c; }
        __syncthreads();
        if (q == 0) {
            g_A[s * 128 + d] = a + pa[0][d] + pa[1][d] + pa[2][d];
            g_C[s * 128 + d] = c + pc[0][d] + pc[1][d] + pc[2][d] + tp_b2[d];
        }
    } else {
        __shared__ float s[32][33];
        const int blk = blockIdx.x - 129;
        const int bx = blk & 15;
        const int by = blk >> 4;
        if (tid < 256) {
            const int c = tid & 31;
            const int r8 = tid >> 5;
            #pragma unroll
            for (int p = 0; p < 4; p++) {
                const int r = r8 + p * 8;
                s[r][c] = em_w1[(bx * 32 + r) * 128 + by * 32 + c];
            }
        }
        __syncthreads();
        if (tid < 256) {
            const int c = tid & 31;
            const int r8 = tid >> 5;
            #pragma unroll
            for (int p = 0; p < 4; p++) {
                const int r = r8 + p * 8;
                const int n = by * 32 + r;
                const float v = s[c][r];
                const __nv_bfloat16 hb = __float2bfloat16_rn(v);
                const float rres = v - __bfloat162float(hb);
                const __nv_bfloat16 lb = __float2bfloat16_rn(rres);
                g_Whi[n * 512 + bx * 32 + c] = __bfloat16_as_ushort(hb);
                g_Wlo[n * 512 + bx * 32 + c] = __bfloat16_as_ushort(lb);
            }
        }
    }
}

// =========================================================================
// encode mainloop for one (node, qt) task. mt_l/dl_l/val_l are per-lane meta
// (lane k < KN owns neighbor k). Returns the attention-pooled embedding.
// =========================================================================
__device__ __forceinline__ float4 encode_task(
    const int lane, const float4 q4,
    unsigned mt_l, float dl_l, bool val_l,
    const float4* __restrict__ nemb4,
    const float4* __restrict__ A4,
    const float4* __restrict__ C4,
    const float4* __restrict__ semb4)
{
    const unsigned vball = __ballot_sync(0xffffffffu, val_l);
    const unsigned sball = __ballot_sync(0xffffffffu,
        (lane < KN) && (((mt_l >> 17) & 0xFFu) == 128u));
    const unsigned contrib = vball ? vball : 0xFFFFFu;
    const bool fast = ((contrib & ~sball) == 0u);

    const int nv = __popc(contrib);
    const int idx = (lane < nv) ? lane : (nv - 1);
    const int pos = __fns(contrib, 0, idx + 1);
    unsigned cmt = __shfl_sync(0xffffffffu, mt_l, pos);
    const float cdl = __shfl_sync(0xffffffffu, dl_l, pos);
    if (lane >= nv) cmt &= ~(1u << 26);
    const int ngroups = (nv + 3) >> 2;

    const float rsH = 0.08838834764831845f;
    float m = -INFINITY;
    float ssum = 0.0f;

    unsigned mt[4]; float dl[4]; float4 em[4];
    #pragma unroll
    for (int i = 0; i < 4; i++) {
        mt[i] = __shfl_sync(0xffffffffu, cmt, i);
        dl[i] = __shfl_sync(0xffffffffu, cdl, i);
        em[i] = __ldg(&nemb4[(mt[i] & 0x1FFFFu) * 32 + lane]);
    }

    float4 outv;

    if (fast) {
        float qa, qc, qs0, qs1;
        {
            const float4 a128 = __ldg(&A4[128 * 32 + lane]);
            const float4 c128 = __ldg(&C4[128 * 32 + lane]);
            const float4 se0 = __ldg(&semb4[lane]);
            const float4 se1 = __ldg(&semb4[32 + lane]);
            reduce4(lane, dot4(a128, q4), dot4(c128, q4),
                    dot4(se0, q4), dot4(se1, q4), qa, qc, qs0, qs1);
        }

        float wd = 0.0f, ws0 = 0.0f;
        float4 acc = make_float4(0.f, 0.f, 0.f, 0.f);

        for (int g = 0; g < ngroups; g++) {
            unsigned mtn[4]; float dln[4]; float4 emn[4];
            const bool more = (g + 1 < ngroups);
            if (more) {
                #pragma unroll
                for (int i = 0; i < 4; i++) {
                    const int j = (g + 1) * 4 + i;
                    mtn[i] = __shfl_sync(0xffffffffu, cmt, j);
                    dln[i] = __shfl_sync(0xffffffffu, cdl, j);
                    emn[i] = __ldg(&nemb4[(mtn[i] & 0x1FFFFu) * 32 + lane]);
                }
            }

            float t0, t1, t2, t3;
            reduce4(lane, dot4(em[0], q4), dot4(em[1], q4),
                    dot4(em[2], q4), dot4(em[3], q4), t0, t1, t2, t3);

            const float a0 = fmaf(qa, dl[0], qc) + ((mt[0] & (1u << 25)) ? qs1 : qs0);
            const float a1 = fmaf(qa, dl[1], qc) + ((mt[1] & (1u << 25)) ? qs1 : qs0);
            const float a2 = fmaf(qa, dl[2], qc) + ((mt[2] & (1u << 25)) ? qs1 : qs0);
            const float a3 = fmaf(qa, dl[3], qc) + ((mt[3] & (1u << 25)) ? qs1 : qs0);

            const float sc0 = (mt[0] & (1u << 26)) ? (t0 + a0) * rsH : NEGV;
            const float sc1 = (mt[1] & (1u << 26)) ? (t1 + a1) * rsH : NEGV;
            const float sc2 = (mt[2] & (1u << 26)) ? (t2 + a2) * rsH : NEGV;
            const float sc3 = (mt[3] & (1u << 26)) ? (t3 + a3) * rsH : NEGV;

            const float mn = fmaxf(m, fmaxf(fmaxf(sc0, sc1), fmaxf(sc2, sc3)));
            const float f  = __expf(m - mn);
            const float w0 = __expf(sc0 - mn);
            const float w1 = __expf(sc1 - mn);
            const float w2 = __expf(sc2 - mn);
            const float w3 = __expf(sc3 - mn);
            ssum = fmaf(ssum, f, w0 + w1 + w2 + w3);
            wd = fmaf(wd, f, fmaf(w0, dl[0], fmaf(w1, dl[1],
                        fmaf(w2, dl[2], w3 * dl[3]))));
            ws0 = fmaf(ws0, f,
                  ((mt[0] & (1u << 25)) ? 0.0f : w0) +
                  ((mt[1] & (1u << 25)) ? 0.0f : w1) +
                  ((mt[2] & (1u << 25)) ? 0.0f : w2) +
                  ((mt[3] & (1u << 25)) ? 0.0f : w3));
            acc.x = fmaf(w3, em[3].x, fmaf(w2, em[2].x, fmaf(w1, em[1].x, fmaf(w0, em[0].x, acc.x * f))));
            acc.y = fmaf(w3, em[3].y, fmaf(w2, em[2].y, fmaf(w1, em[1].y, fmaf(w0, em[0].y, acc.y * f))));
            acc.z = fmaf(w3, em[3].z, fmaf(w2, em[2].z, fmaf(w1, em[1].z, fmaf(w0, em[0].z, acc.z * f))));
            acc.w = fmaf(w3, em[3].w, fmaf(w2, em[2].w, fmaf(w1, em[1].w, fmaf(w0, em[0].w, acc.w * f))));
            m = mn;

            if (more) {
                #pragma unroll
                for (int i = 0; i < 4; i++) { mt[i] = mtn[i]; dl[i] = dln[i]; em[i] = emn[i]; }
            }
        }

        const float inv = 1.0f / ssum;
        const float f0 = ws0 * inv;
        const float f1 = (ssum - ws0) * inv;
        const float wdn = wd * inv;
        const float4 a128 = __ldg(&A4[128 * 32 + lane]);
        const float4 c128 = __ldg(&C4[128 * 32 + lane]);
        const float4 se0 = __ldg(&semb4[lane]);
        const float4 se1 = __ldg(&semb4[32 + lane]);
        outv.x = fmaf(acc.x, inv, fmaf(a128.x, wdn, fmaf(se0.x, f0, fmaf(se1.x, f1, c128.x))));
        outv.y = fmaf(acc.y, inv, fmaf(a128.y, wdn, fmaf(se0.y, f0, fmaf(se1.y, f1, c128.y))));
        outv.z = fmaf(acc.z, inv, fmaf(a128.z, wdn, fmaf(se0.z, f0, fmaf(se1.z, f1, c128.z))));
        outv.w = fmaf(acc.w, inv, fmaf(a128.w, wdn, fmaf(se0.w, f0, fmaf(se1.w, f1, c128.w))));
    } else {
        const float4 se0 = __ldg(&semb4[lane]);
        const float4 se1 = __ldg(&semb4[32 + lane]);
        float4 acc = make_float4(0.f, 0.f, 0.f, 0.f);

        for (int g = 0; g < ngroups; g++) {
            unsigned mtn[4]; float dln[4]; float4 emn[4];
            const bool more = (g + 1 < ngroups);
            if (more) {
                #pragma unroll
                for (int i = 0; i < 4; i++) {
                    const int j = (g + 1) * 4 + i;
                    mtn[i] = __shfl_sync(0xffffffffu, cmt, j);
                    dln[i] = __shfl_sync(0xffffffffu, cdl, j);
                    emn[i] = __ldg(&nemb4[(mtn[i] & 0x1FFFFu) * 32 + lane]);
                }
            }

            float4 kv[4]; float dp[4];
            #pragma unroll
            for (int i = 0; i < 4; i++) {
                const int seg = (mt[i] >> 17) & 0xFF;
                const float4 sg4 = (mt[i] & (1u << 25)) ? se1 : se0;
                const float4 a4 = A4[seg * 32 + lane];
                const float4 c4 = C4[seg * 32 + lane];
                kv[i].x = em[i].x + sg4.x + fmaf(a4.x, dl[i], c4.x);
                kv[i].y = em[i].y + sg4.y + fmaf(a4.y, dl[i], c4.y);
                kv[i].z = em[i].z + sg4.z + fmaf(a4.z, dl[i], c4.z);
                kv[i].w = em[i].w + sg4.w + fmaf(a4.w, dl[i], c4.w);
                dp[i] = dot4(kv[i], q4);
            }

            float t0, t1, t2, t3;
            reduce4(lane, dp[0], dp[1], dp[2], dp[3], t0, t1, t2, t3);

            const float sc0 = (mt[0] & (1u << 26)) ? t0 * rsH : NEGV;
            const float sc1 = (mt[1] & (1u << 26)) ? t1 * rsH : NEGV;
            const float sc2 = (mt[2] & (1u << 26)) ? t2 * rsH : NEGV;
            const float sc3 = (mt[3] & (1u << 26)) ? t3 * rsH : NEGV;

            const float mn = fmaxf(m, fmaxf(fmaxf(sc0, sc1), fmaxf(sc2, sc3)));
            const float f  = __expf(m - mn);
            const float w0 = __expf(sc0 - mn);
            const float w1 = __expf(sc1 - mn);
            const float w2 = __expf(sc2 - mn);
            const float w3 = __expf(sc3 - mn);
            ssum = fmaf(ssum, f, w0 + w1 + w2 + w3);
            acc.x = fmaf(w3, kv[3].x, fmaf(w2, kv[2].x, fmaf(w1, kv[1].x, fmaf(w0, kv[0].x, acc.x * f))));
            acc.y = fmaf(w3, kv[3].y, fmaf(w2, kv[2].y, fmaf(w1, kv[1].y, fmaf(w0, kv[0].y, acc.y * f))));
            acc.z = fmaf(w3, kv[3].z, fmaf(w2, kv[2].z, fmaf(w1, kv[1].z, fmaf(w0, kv[0].z, acc.z * f))));
            acc.w = fmaf(w3, kv[3].w, fmaf(w2, kv[2].w, fmaf(w1, kv[1].w, fmaf(w0, kv[0].w, acc.w * f))));
            m = mn;

            if (more) {
                #pragma unroll
                for (int i = 0; i < 4; i++) { mt[i] = mtn[i]; dl[i] = dln[i]; em[i] = emn[i]; }
            }
        }

        const float inv = 1.0f / ssum;
        outv.x = acc.x * inv; outv.y = acc.y * inv;
        outv.z = acc.z * inv; outv.w = acc.w * inv;
    }
    return outv;
}

// =========================================================================
// Kernel 2: one warp handles BOTH sides of one edge (shared qt; both
// prologue chains issued together -> per-task exposed latency halves).
// =========================================================================
__global__ void __launch_bounds__(256, 3) encode_kernel(
    const int*   __restrict__ edge_index,
    const int*   __restrict__ ets,
    const int*   __restrict__ hnb,
    const int*   __restrict__ hts,
    const int*   __restrict__ hsg,
    const float* __restrict__ nemb,
    const float* __restrict__ semb)
{
    __shared__ float sbp[128];
    if (threadIdx.x < 128) sbp[threadIdx.x] = g_bp[threadIdx.x];
    __syncthreads();

    const int w    = threadIdx.x >> 5;
    const int lane = threadIdx.x & 31;
    const int e    = blockIdx.x * 8 + w;     // NB edges, 8 warps/block

    const int qt   = ets[e];
    const float qtf = (float)qt;
    const int nodeU = edge_index[e];
    const int nodeV = edge_index[NB + e];

    const float4* nemb4 = (const float4*)nemb;
    const float4* A4 = (const float4*)g_A;
    const float4* C4 = (const float4*)g_C;
    const float4* semb4 = (const float4*)semb;

    const float4 q4U = __ldg(&nemb4[nodeU * 32 + lane]);
    const float4 q4V = __ldg(&nemb4[nodeV * 32 + lane]);
    const float bpmin = sbp[0];
    const float bpmax = sbp[127];

    // ---- per-lane meta for both sides (loads issued together) ----
    int nbU = -1, htU = 0, sgU = 0, nbV = -1, htV = 0, sgV = 0;
    if (lane < KN) {
        nbU = hnb[nodeU * KN + lane];
        nbV = hnb[nodeV * KN + lane];
        htU = hts[nodeU * KN + lane];
        htV = hts[nodeV * KN + lane];
        sgU = hsg[nodeU * KN + lane];
        sgV = hsg[nodeV * KN + lane];
    }

    unsigned mtl[2] = {0u, 0u};
    float    dll[2] = {0.0f, 0.0f};
    bool     vll[2] = {false, false};
    if (lane < KN) {
        #pragma unroll
        for (int s = 0; s < 2; s++) {
            const int nb = s ? nbV : nbU;
            const int ht = s ? htV : htU;
            const int sg = s ? sgV : sgU;
            const float delta = qtf - (float)ht;
            int seg;
            if (delta > bpmax) {
                seg = 128;
            } else if (delta <= bpmin) {
                seg = 0;
            } else {
                int lo = 0, hi = 128;
                #pragma unroll
                for (int it = 0; it < 7; it++) {
                    const int mid = (lo + hi) >> 1;
                    if (sbp[mid] < delta) lo = mid + 1; else hi = mid;
                }
                seg = lo;
            }
            const bool valid = (nb != -1) && (ht < qt);
            const unsigned nbc = (nb == -1) ? 0u : (unsigned)nb;
            mtl[s] = nbc | ((unsigned)seg << 17) | ((unsigned)sg << 25)
                        | (valid ? (1u << 26) : 0u);
            dll[s] = delta;
            vll[s] = valid;
        }
    }

    const float4 zu = encode_task(lane, q4U, mtl[0], dll[0], vll[0],
                                  nemb4, A4, C4, semb4);
    ((float4*)g_z)[(unsigned)e * 32 + lane] = zu;

    const float4 zv = encode_task(lane, q4V, mtl[1], dll[1], vll[1],
                                  nemb4, A4, C4, semb4);
    ((float4*)g_z)[(unsigned)(NB + e) * 32 + lane] = zv;
}

// =========================================================================
// Kernel 3: split-bf16 mma.sync GEMM MLP (unchanged).
// =========================================================================
#define MMA_BF16(C, A, B0, B1) \
    asm volatile("mma.sync.aligned.m16n8k16.row.col.f32.bf16.bf16.f32 " \
        "{%0,%1,%2,%3}, {%4,%5,%6,%7}, {%8,%9}, {%0,%1,%2,%3};" \
        : "+f"((C)[0]), "+f"((C)[1]), "+f"((C)[2]), "+f"((C)[3]) \
        : "r"((A)[0]), "r"((A)[1]), "r"((A)[2]), "r"((A)[3]), "r"(B0), "r"(B1))

#define LDSM_X4(R, addr) \
    asm volatile("ldmatrix.sync.aligned.m8n8.x4.shared.b16 {%0,%1,%2,%3}, [%4];" \
        : "=r"((R)[0]), "=r"((R)[1]), "=r"((R)[2]), "=r"((R)[3]) : "r"(addr))

#define REGION_SZ 18432
#define BUF_SZ    (4 * REGION_SZ)

extern __shared__ char dsm[];
__global__ void __launch_bounds__(256, 2) mlp_mma_kernel(
    const float* __restrict__ b1,
    const float* __restrict__ w2,
    const float* __restrict__ b2,
    float*       __restrict__ out)
{
    __shared__ float slog[128];

    const int tid  = threadIdx.x;
    const int wid  = tid >> 5;
    const int lane = tid & 31;
    const int e0   = blockIdx.x * 128;

    char* sAhi = dsm;
    char* sAlo = dsm + REGION_SZ;
    char* sBhi = dsm + 2 * REGION_SZ;
    char* sBlo = dsm + 3 * REGION_SZ;

    if (tid < 128) slog[tid] = 0.0f;

    const int wm = wid >> 1;
    const int wn = wid & 1;
    const int g  = lane >> 2;
    const int t2 = (lane & 3) * 2;

    const uint32_t uAhi = (uint32_t)__cvta_generic_to_shared(sAhi);
    const uint32_t uAlo = uAhi + REGION_SZ;
    const uint32_t uBhi = uAhi + 2 * REGION_SZ;
    const uint32_t uBlo = uAhi + 3 * REGION_SZ;
    const int lm = lane >> 3;
    const int lr = lane & 7;
    const uint32_t aofs = (uint32_t)(((lm & 1) * 8 + lr) * 144 + (lm >> 1) * 16);
    const uint32_t bofs = (uint32_t)(((lm >> 1) * 8 + lr) * 144 + (lm & 1) * 16);
    const uint32_t aRow0 = (uint32_t)((wm * 32) * 144);
    const uint32_t aRow1 = (uint32_t)((wm * 32 + 16) * 144);
    const uint32_t bBase = (uint32_t)((wn * 64) * 144);

    float acc[2][8][4];
    #pragma unroll
    for (int mt = 0; mt < 2; mt++)
        #pragma unroll
        for (int nt = 0; nt < 8; nt++)
            #pragma unroll
            for (int u = 0; u < 4; u++)
                acc[mt][nt][u] = 0.0f;

    const int f4 = tid & 15;
    const int r0 = tid >> 4;
    const int bn = tid >> 1;
    const int bhk = tid & 1;

    for (int chunk = 0; chunk < 8; chunk++) {
        const int region = chunk >> 1;
        const int cb4 = (chunk & 1) * 16;
        __syncthreads();

        #pragma unroll
        for (int i = 0; i < 4; i++) {
            const int kk = chunk * 64 + bhk * 32 + i * 8;
            const int so = bn * 144 + (bhk * 32 + i * 8) * 2;
            cp16(sBhi + so, &g_Whi[bn * 512 + kk]);
            cp16(sBlo + so, &g_Wlo[bn * 512 + kk]);
        }
        CP_COMMIT();

        #pragma unroll
        for (int p = 0; p < 8; p++) {
            const int r = r0 + p * 16;
            float4 v;
            if (region == 0) {
                v = ((const float4*)g_z)[(unsigned)(e0 + r) * 32 + cb4 + f4];
            } else if (region == 1) {
                v = ((const float4*)g_z)[(unsigned)(NB + e0 + r) * 32 + cb4 + f4];
            } else {
                const float4 a = ((const float4*)g_z)[(unsigned)(e0 + r) * 32 + cb4 + f4];
                const float4 b = ((const float4*)g_z)[(unsigned)(NB + e0 + r) * 32 + cb4 + f4];
                if (region == 2) {
                    v.x = fabsf(a.x - b.x); v.y = fabsf(a.y - b.y);
                    v.z = fabsf(a.z - b.z); v.w = fabsf(a.w - b.w);
                } else {
                    v.x = a.x * b.x; v.y = a.y * b.y;
                    v.z = a.z * b.z; v.w = a.w * b.w;
                }
            }
            uint2 hv, lv;
            hv.x = cvt_bf16x2(v.x, v.y);
            hv.y = cvt_bf16x2(v.z, v.w);
            const float hxf = __uint_as_float(hv.x << 16);
            const float hyf = __uint_as_float(hv.x & 0xFFFF0000u);
            const float hzf = __uint_as_float(hv.y << 16);
            const float hwf = __uint_as_float(hv.y & 0xFFFF0000u);
            lv.x = cvt_bf16x2(v.x - hxf, v.y - hyf);
            lv.y = cvt_bf16x2(v.z - hzf, v.w - hwf);
            *(uint2*)(sAhi + r * 144 + f4 * 8) = hv;
            *(uint2*)(sAlo + r * 144 + f4 * 8) = lv;
        }
        CP_WAIT0();
        __syncthreads();

        #pragma unroll
        for (int ks = 0; ks < 4; ks++) {
            const uint32_t kof = (uint32_t)(ks * 32);
            uint32_t ah[2][4], al[2][4];
            LDSM_X4(ah[0], uAhi + aRow0 + aofs + kof);
            LDSM_X4(ah[1], uAhi + aRow1 + aofs + kof);
            LDSM_X4(al[0], uAlo + aRow0 + aofs + kof);
            LDSM_X4(al[1], uAlo + aRow1 + aofs + kof);

            uint32_t bh0[8], bh1[8], bl0[8], bl1[8];
            #pragma unroll
            for (int p = 0; p < 4; p++) {
                uint32_t rh[4], rl[4];
                LDSM_X4(rh, uBhi + bBase + (uint32_t)(p * 16 * 144) + bofs + kof);
                LDSM_X4(rl, uBlo + bBase + (uint32_t)(p * 16 * 144) + bofs + kof);
                bh0[2 * p] = rh[0]; bh1[2 * p] = rh[1];
                bh0[2 * p + 1] = rh[2]; bh1[2 * p + 1] = rh[3];
                bl0[2 * p] = rl[0]; bl1[2 * p] = rl[1];
                bl0[2 * p + 1] = rl[2]; bl1[2 * p + 1] = rl[3];
            }

            #pragma unroll
            for (int nt = 0; nt < 8; nt++) {
                #pragma unroll
                for (int mt = 0; mt < 2; mt++) {
                    MMA_BF16(acc[mt][nt], ah[mt], bh0[nt], bh1[nt]);
                    MMA_BF16(acc[mt][nt], ah[mt], bl0[nt], bl1[nt]);
                    MMA_BF16(acc[mt][nt], al[mt], bh0[nt], bh1[nt]);
                }
            }
        }
    }
    __syncthreads();

    float b1v[16], w2v[16];
    #pragma unroll
    for (int nt = 0; nt < 8; nt++) {
        const int n = wn * 64 + nt * 8 + t2;
        b1v[nt * 2]     = __ldg(&b1[n]);
        b1v[nt * 2 + 1] = __ldg(&b1[n + 1]);
        w2v[nt * 2]     = __ldg(&w2[n]);
        w2v[nt * 2 + 1] = __ldg(&w2[n + 1]);
    }
    #pragma unroll
    for (int mt = 0; mt < 2; mt++) {
        float p1 = 0.0f, p2 = 0.0f;
        #pragma unroll
        for (int nt = 0; nt < 8; nt++) {
            p1 += fmaxf(acc[mt][nt][0] + b1v[2 * nt],     0.0f) * w2v[2 * nt]
                + fmaxf(acc[mt][nt][1] + b1v[2 * nt + 1], 0.0f) * w2v[2 * nt + 1];
            p2 += fmaxf(acc[mt][nt][2] + b1v[2 * nt],     0.0f) * w2v[2 * nt]
                + fmaxf(acc[mt][nt][3] + b1v[2 * nt + 1], 0.0f) * w2v[2 * nt + 1];
        }
        const int r1 = wm * 32 + mt * 16 + g;
        atomicAdd(&slog[r1], p1);
        atomicAdd(&slog[r1 + 8], p2);
    }
    __syncthreads();
    if (tid < 128) out[e0 + tid] = slog[tid] + b2[0];
}

// =========================================================================
extern "C" void kernel_launch(void* const* d_in, const int* in_sizes, int n_in,
                              void* d_out, int out_size)
{
    const int*   edge_index = (const int*)  d_in[0];
    const int*   ets        = (const int*)  d_in[1];
    const int*   hnb        = (const int*)  d_in[2];
    const int*   hts        = (const int*)  d_in[3];
    const int*   hsg        = (const int*)  d_in[4];
    const float* nemb       = (const float*)d_in[5];
    const float* semb       = (const float*)d_in[6];
    const float* tp_w1      = (const float*)d_in[7];
    const float* tp_b1      = (const float*)d_in[8];
    const float* tp_w2      = (const float*)d_in[9];
    const float* tp_b2      = (const float*)d_in[10];
    const float* em_w1      = (const float*)d_in[11];
    const float* em_b1      = (const float*)d_in[12];
    const float* em_w2      = (const float*)d_in[13];
    const float* em_b2      = (const float*)d_in[14];
    float* out = (float*)d_out;

    cudaFuncSetAttribute(mlp_mma_kernel,
                         cudaFuncAttributeMaxDynamicSharedMemorySize, BUF_SZ);

    prolog_kernel<<<193, 512>>>(tp_w1, tp_b1, tp_w2, tp_b2, em_w1);
    encode_kernel<<<NB / 8, 256>>>(edge_index, ets, hnb, hts, hsg, nemb, semb);
    mlp_mma_kernel<<<NB / 128, 256, BUF_SZ>>>(em_b1, em_w2, em_b2, out);
}

// round 17
// speedup vs baseline: 1.3473x; 1.0403x over previous
#include <cuda_runtime.h>
#include <cuda_bf16.h>
#include <math.h>
#include <stdint.h>

#define H 128
#define KN 20
#define NB 65536
#define NEGV (-1e9f)

// ---------------- device scratch ----------------
__device__ float g_A[129 * 128];
__device__ float g_C[129 * 128];
__device__ float g_bp[128];
__device__ float g_z[2u * NB * 128];                 // zu | zv
__device__ unsigned short g_Whi[128 * 512];          // W1^T hi (bf16 bits) [n][k]
__device__ unsigned short g_Wlo[128 * 512];          // W1^T lo

__device__ __forceinline__ void cp16(void* smem, const void* gmem) {
    const uint32_t s = (uint32_t)__cvta_generic_to_shared(smem);
    asm volatile("cp.async.cg.shared.global [%0], [%1], 16;"
                 :: "r"(s), "l"(__cvta_generic_to_global(gmem)) : "memory");
}
#define CP_COMMIT() asm volatile("cp.async.commit_group;" ::: "memory")
#define CP_WAIT0()  asm volatile("cp.async.wait_group 0;" ::: "memory")

__device__ __forceinline__ uint32_t cvt_bf16x2(float x, float y) {
    uint32_t r;
    asm("cvt.rn.bf16x2.f32 %0, %1, %2;" : "=r"(r) : "f"(y), "f"(x));
    return r;
}

__device__ __forceinline__ float dot4(float4 a, float4 b) {
    return fmaf(a.x, b.x, fmaf(a.y, b.y, fmaf(a.z, b.z, a.w * b.w)));
}

// merged 4-way butterfly: reduces 4 independent values, broadcasts totals.
__device__ __forceinline__ void reduce4(int lane, float d0, float d1, float d2, float d3,
                                        float& t0, float& t1, float& t2, float& t3)
{
    const float r0 = d0 + __shfl_xor_sync(0xffffffffu, d0, 16);
    const float r1 = d1 + __shfl_xor_sync(0xffffffffu, d1, 16);
    const float r2 = d2 + __shfl_xor_sync(0xffffffffu, d2, 16);
    const float r3 = d3 + __shfl_xor_sync(0xffffffffu, d3, 16);
    const float m01 = (lane & 16) ? r1 : r0;
    const float m23 = (lane & 16) ? r3 : r2;
    const float q01 = m01 + __shfl_xor_sync(0xffffffffu, m01, 8);
    const float q23 = m23 + __shfl_xor_sync(0xffffffffu, m23, 8);
    float mm = (lane & 8) ? q23 : q01;
    mm += __shfl_xor_sync(0xffffffffu, mm, 4);
    mm += __shfl_xor_sync(0xffffffffu, mm, 2);
    mm += __shfl_xor_sync(0xffffffffu, mm, 1);
    t0 = __shfl_sync(0xffffffffu, mm, 0);
    t1 = __shfl_sync(0xffffffffu, mm, 16);
    t2 = __shfl_sync(0xffffffffu, mm, 8);
    t3 = __shfl_sync(0xffffffffu, mm, 24);
}

// =========================================================================
// Kernel 1 (merged): blocks 0..128 -> piecewise-linear decomposition;
// blocks 129..192 -> W1 transpose + bf16 hi/lo split.
// =========================================================================
__global__ void __launch_bounds__(512) prolog_kernel(
    const float* __restrict__ tp_w1, const float* __restrict__ tp_b1,
    const float* __restrict__ tp_w2, const float* __restrict__ tp_b2,
    const float* __restrict__ em_w1)
{
    const int tid = threadIdx.x;

    if (blockIdx.x < 129) {
        __shared__ float sw[128], sb[128], sbp[128];
        __shared__ int   srank[128];
        __shared__ float pa[3][128], pc[3][128];

        if (tid < 128) {
            const float w = tp_w1[tid], b = tp_b1[tid];
            const float bp = (w != 0.0f) ? (-b / w) : INFINITY;
            sw[tid] = w; sb[tid] = b; sbp[tid] = bp;
        }
        __syncthreads();
        if (tid < 128) {
            const float bp = sbp[tid];
            int r = 0;
            #pragma unroll 8
            for (int j = 0; j < 128; j++) {
                const float bj = sbp[j];
                if (bj < bp || (bj == bp && j < tid)) r++;
            }
            srank[tid] = r;
            if (blockIdx.x == 0) g_bp[r] = bp;
        }
        __syncthreads();

        const int s = blockIdx.x;
        const int d = tid & 127;
        const int q = tid >> 7;
        float a = 0.0f, c = 0.0f;
        #pragma unroll 8
        for (int jj = 0; jj < 32; jj++) {
            const int j = q * 32 + jj;
            const float wj = sw[j];
            bool active;
            if (wj > 0.0f)      active = (srank[j] < s);
            else if (wj < 0.0f) active = (srank[j] >= s);
            else                active = (sb[j] > 0.0f);
            if (active) {
                const float w2v = __ldg(&tp_w2[j * 128 + d]);
                a = fmaf(wj, w2v, a);
                c = fmaf(sb[j], w2v, c);
            }
        }
        if (q) { pa[q - 1][d] = a; pc[q - 1][d] = c; }
        __syncthreads();
        if (q == 0) {
            g_A[s * 128 + d] = a + pa[0][d] + pa[1][d] + pa[2][d];
            g_C[s * 128 + d] = c + pc[0][d] + pc[1][d] + pc[2][d] + tp_b2[d];
        }
    } else {
        __shared__ float s[32][33];
        const int blk = blockIdx.x - 129;
        const int bx = blk & 15;
        const int by = blk >> 4;
        if (tid < 256) {
            const int c = tid & 31;
            const int r8 = tid >> 5;
            #pragma unroll
            for (int p = 0; p < 4; p++) {
                const int r = r8 + p * 8;
                s[r][c] = em_w1[(bx * 32 + r) * 128 + by * 32 + c];
            }
        }
        __syncthreads();
        if (tid < 256) {
            const int c = tid & 31;
            const int r8 = tid >> 5;
            #pragma unroll
            for (int p = 0; p < 4; p++) {
                const int r = r8 + p * 8;
                const int n = by * 32 + r;
                const float v = s[c][r];
                const __nv_bfloat16 hb = __float2bfloat16_rn(v);
                const float rres = v - __bfloat162float(hb);
                const __nv_bfloat16 lb = __float2bfloat16_rn(rres);
                g_Whi[n * 512 + bx * 32 + c] = __bfloat16_as_ushort(hb);
                g_Wlo[n * 512 + bx * 32 + c] = __bfloat16_as_ushort(lb);
            }
        }
    }
}

// =========================================================================
// encode mainloop for one (node, qt) task.  (unchanged from round 15)
// =========================================================================
__device__ __forceinline__ float4 encode_task(
    const int lane, const float4 q4,
    unsigned mt_l, float dl_l, bool val_l,
    const float4* __restrict__ nemb4,
    const float4* __restrict__ A4,
    const float4* __restrict__ C4,
    const float4* __restrict__ semb4)
{
    const unsigned vball = __ballot_sync(0xffffffffu, val_l);
    const unsigned sball = __ballot_sync(0xffffffffu,
        (lane < KN) && (((mt_l >> 17) & 0xFFu) == 128u));
    const unsigned contrib = vball ? vball : 0xFFFFFu;
    const bool fast = ((contrib & ~sball) == 0u);

    const int nv = __popc(contrib);
    const int idx = (lane < nv) ? lane : (nv - 1);
    const int pos = __fns(contrib, 0, idx + 1);
    unsigned cmt = __shfl_sync(0xffffffffu, mt_l, pos);
    const float cdl = __shfl_sync(0xffffffffu, dl_l, pos);
    if (lane >= nv) cmt &= ~(1u << 26);
    const int ngroups = (nv + 3) >> 2;

    const float rsH = 0.08838834764831845f;
    float m = -INFINITY;
    float ssum = 0.0f;

    unsigned mt[4]; float dl[4]; float4 em[4];
    #pragma unroll
    for (int i = 0; i < 4; i++) {
        mt[i] = __shfl_sync(0xffffffffu, cmt, i);
        dl[i] = __shfl_sync(0xffffffffu, cdl, i);
        em[i] = __ldg(&nemb4[(mt[i] & 0x1FFFFu) * 32 + lane]);
    }

    float4 outv;

    if (fast) {
        float qa, qc, qs0, qs1;
        {
            const float4 a128 = __ldg(&A4[128 * 32 + lane]);
            const float4 c128 = __ldg(&C4[128 * 32 + lane]);
            const float4 se0 = __ldg(&semb4[lane]);
            const float4 se1 = __ldg(&semb4[32 + lane]);
            reduce4(lane, dot4(a128, q4), dot4(c128, q4),
                    dot4(se0, q4), dot4(se1, q4), qa, qc, qs0, qs1);
        }

        float wd = 0.0f, ws0 = 0.0f;
        float4 acc = make_float4(0.f, 0.f, 0.f, 0.f);

        for (int g = 0; g < ngroups; g++) {
            unsigned mtn[4]; float dln[4]; float4 emn[4];
            const bool more = (g + 1 < ngroups);
            if (more) {
                #pragma unroll
                for (int i = 0; i < 4; i++) {
                    const int j = (g + 1) * 4 + i;
                    mtn[i] = __shfl_sync(0xffffffffu, cmt, j);
                    dln[i] = __shfl_sync(0xffffffffu, cdl, j);
                    emn[i] = __ldg(&nemb4[(mtn[i] & 0x1FFFFu) * 32 + lane]);
                }
            }

            float t0, t1, t2, t3;
            reduce4(lane, dot4(em[0], q4), dot4(em[1], q4),
                    dot4(em[2], q4), dot4(em[3], q4), t0, t1, t2, t3);

            const float a0 = fmaf(qa, dl[0], qc) + ((mt[0] & (1u << 25)) ? qs1 : qs0);
            const float a1 = fmaf(qa, dl[1], qc) + ((mt[1] & (1u << 25)) ? qs1 : qs0);
            const float a2 = fmaf(qa, dl[2], qc) + ((mt[2] & (1u << 25)) ? qs1 : qs0);
            const float a3 = fmaf(qa, dl[3], qc) + ((mt[3] & (1u << 25)) ? qs1 : qs0);

            const float sc0 = (mt[0] & (1u << 26)) ? (t0 + a0) * rsH : NEGV;
            const float sc1 = (mt[1] & (1u << 26)) ? (t1 + a1) * rsH : NEGV;
            const float sc2 = (mt[2] & (1u << 26)) ? (t2 + a2) * rsH : NEGV;
            const float sc3 = (mt[3] & (1u << 26)) ? (t3 + a3) * rsH : NEGV;

            const float mn = fmaxf(m, fmaxf(fmaxf(sc0, sc1), fmaxf(sc2, sc3)));
            const float f  = __expf(m - mn);
            const float w0 = __expf(sc0 - mn);
            const float w1 = __expf(sc1 - mn);
            const float w2 = __expf(sc2 - mn);
            const float w3 = __expf(sc3 - mn);
            ssum = fmaf(ssum, f, w0 + w1 + w2 + w3);
            wd = fmaf(wd, f, fmaf(w0, dl[0], fmaf(w1, dl[1],
                        fmaf(w2, dl[2], w3 * dl[3]))));
            ws0 = fmaf(ws0, f,
                  ((mt[0] & (1u << 25)) ? 0.0f : w0) +
                  ((mt[1] & (1u << 25)) ? 0.0f : w1) +
                  ((mt[2] & (1u << 25)) ? 0.0f : w2) +
                  ((mt[3] & (1u << 25)) ? 0.0f : w3));
            acc.x = fmaf(w3, em[3].x, fmaf(w2, em[2].x, fmaf(w1, em[1].x, fmaf(w0, em[0].x, acc.x * f))));
            acc.y = fmaf(w3, em[3].y, fmaf(w2, em[2].y, fmaf(w1, em[1].y, fmaf(w0, em[0].y, acc.y * f))));
            acc.z = fmaf(w3, em[3].z, fmaf(w2, em[2].z, fmaf(w1, em[1].z, fmaf(w0, em[0].z, acc.z * f))));
            acc.w = fmaf(w3, em[3].w, fmaf(w2, em[2].w, fmaf(w1, em[1].w, fmaf(w0, em[0].w, acc.w * f))));
            m = mn;

            if (more) {
                #pragma unroll
                for (int i = 0; i < 4; i++) { mt[i] = mtn[i]; dl[i] = dln[i]; em[i] = emn[i]; }
            }
        }

        const float inv = 1.0f / ssum;
        const float f0 = ws0 * inv;
        const float f1 = (ssum - ws0) * inv;
        const float wdn = wd * inv;
        const float4 a128 = __ldg(&A4[128 * 32 + lane]);
        const float4 c128 = __ldg(&C4[128 * 32 + lane]);
        const float4 se0 = __ldg(&semb4[lane]);
        const float4 se1 = __ldg(&semb4[32 + lane]);
        outv.x = fmaf(acc.x, inv, fmaf(a128.x, wdn, fmaf(se0.x, f0, fmaf(se1.x, f1, c128.x))));
        outv.y = fmaf(acc.y, inv, fmaf(a128.y, wdn, fmaf(se0.y, f0, fmaf(se1.y, f1, c128.y))));
        outv.z = fmaf(acc.z, inv, fmaf(a128.z, wdn, fmaf(se0.z, f0, fmaf(se1.z, f1, c128.z))));
        outv.w = fmaf(acc.w, inv, fmaf(a128.w, wdn, fmaf(se0.w, f0, fmaf(se1.w, f1, c128.w))));
    } else {
        const float4 se0 = __ldg(&semb4[lane]);
        const float4 se1 = __ldg(&semb4[32 + lane]);
        float4 acc = make_float4(0.f, 0.f, 0.f, 0.f);

        for (int g = 0; g < ngroups; g++) {
            unsigned mtn[4]; float dln[4]; float4 emn[4];
            const bool more = (g + 1 < ngroups);
            if (more) {
                #pragma unroll
                for (int i = 0; i < 4; i++) {
                    const int j = (g + 1) * 4 + i;
                    mtn[i] = __shfl_sync(0xffffffffu, cmt, j);
                    dln[i] = __shfl_sync(0xffffffffu, cdl, j);
                    emn[i] = __ldg(&nemb4[(mtn[i] & 0x1FFFFu) * 32 + lane]);
                }
            }

            float4 kv[4]; float dp[4];
            #pragma unroll
            for (int i = 0; i < 4; i++) {
                const int seg = (mt[i] >> 17) & 0xFF;
                const float4 sg4 = (mt[i] & (1u << 25)) ? se1 : se0;
                const float4 a4 = A4[seg * 32 + lane];
                const float4 c4 = C4[seg * 32 + lane];
                kv[i].x = em[i].x + sg4.x + fmaf(a4.x, dl[i], c4.x);
                kv[i].y = em[i].y + sg4.y + fmaf(a4.y, dl[i], c4.y);
                kv[i].z = em[i].z + sg4.z + fmaf(a4.z, dl[i], c4.z);
                kv[i].w = em[i].w + sg4.w + fmaf(a4.w, dl[i], c4.w);
                dp[i] = dot4(kv[i], q4);
            }

            float t0, t1, t2, t3;
            reduce4(lane, dp[0], dp[1], dp[2], dp[3], t0, t1, t2, t3);

            const float sc0 = (mt[0] & (1u << 26)) ? t0 * rsH : NEGV;
            const float sc1 = (mt[1] & (1u << 26)) ? t1 * rsH : NEGV;
            const float sc2 = (mt[2] & (1u << 26)) ? t2 * rsH : NEGV;
            const float sc3 = (mt[3] & (1u << 26)) ? t3 * rsH : NEGV;

            const float mn = fmaxf(m, fmaxf(fmaxf(sc0, sc1), fmaxf(sc2, sc3)));
            const float f  = __expf(m - mn);
            const float w0 = __expf(sc0 - mn);
            const float w1 = __expf(sc1 - mn);
            const float w2 = __expf(sc2 - mn);
            const float w3 = __expf(sc3 - mn);
            ssum = fmaf(ssum, f, w0 + w1 + w2 + w3);
            acc.x = fmaf(w3, kv[3].x, fmaf(w2, kv[2].x, fmaf(w1, kv[1].x, fmaf(w0, kv[0].x, acc.x * f))));
            acc.y = fmaf(w3, kv[3].y, fmaf(w2, kv[2].y, fmaf(w1, kv[1].y, fmaf(w0, kv[0].y, acc.y * f))));
            acc.z = fmaf(w3, kv[3].z, fmaf(w2, kv[2].z, fmaf(w1, kv[1].z, fmaf(w0, kv[0].z, acc.z * f))));
            acc.w = fmaf(w3, kv[3].w, fmaf(w2, kv[2].w, fmaf(w1, kv[1].w, fmaf(w0, kv[0].w, acc.w * f))));
            m = mn;

            if (more) {
                #pragma unroll
                for (int i = 0; i < 4; i++) { mt[i] = mtn[i]; dl[i] = dln[i]; em[i] = emn[i]; }
            }
        }

        const float inv = 1.0f / ssum;
        outv.x = acc.x * inv; outv.y = acc.y * inv;
        outv.z = acc.z * inv; outv.w = acc.w * inv;
    }
    return outv;
}

// =========================================================================
// Kernel 2: one warp handles BOTH sides of one edge. (unchanged)
// =========================================================================
__global__ void __launch_bounds__(256, 3) encode_kernel(
    const int*   __restrict__ edge_index,
    const int*   __restrict__ ets,
    const int*   __restrict__ hnb,
    const int*   __restrict__ hts,
    const int*   __restrict__ hsg,
    const float* __restrict__ nemb,
    const float* __restrict__ semb)
{
    __shared__ float sbp[128];
    if (threadIdx.x < 128) sbp[threadIdx.x] = g_bp[threadIdx.x];
    __syncthreads();

    const int w    = threadIdx.x >> 5;
    const int lane = threadIdx.x & 31;
    const int e    = blockIdx.x * 8 + w;

    const int qt   = ets[e];
    const float qtf = (float)qt;
    const int nodeU = edge_index[e];
    const int nodeV = edge_index[NB + e];

    const float4* nemb4 = (const float4*)nemb;
    const float4* A4 = (const float4*)g_A;
    const float4* C4 = (const float4*)g_C;
    const float4* semb4 = (const float4*)semb;

    const float4 q4U = __ldg(&nemb4[nodeU * 32 + lane]);
    const float4 q4V = __ldg(&nemb4[nodeV * 32 + lane]);
    const float bpmin = sbp[0];
    const float bpmax = sbp[127];

    int nbU = -1, htU = 0, sgU = 0, nbV = -1, htV = 0, sgV = 0;
    if (lane < KN) {
        nbU = hnb[nodeU * KN + lane];
        nbV = hnb[nodeV * KN + lane];
        htU = hts[nodeU * KN + lane];
        htV = hts[nodeV * KN + lane];
        sgU = hsg[nodeU * KN + lane];
        sgV = hsg[nodeV * KN + lane];
    }

    unsigned mtl[2] = {0u, 0u};
    float    dll[2] = {0.0f, 0.0f};
    bool     vll[2] = {false, false};
    if (lane < KN) {
        #pragma unroll
        for (int s = 0; s < 2; s++) {
            const int nb = s ? nbV : nbU;
            const int ht = s ? htV : htU;
            const int sg = s ? sgV : sgU;
            const float delta = qtf - (float)ht;
            int seg;
            if (delta > bpmax) {
                seg = 128;
            } else if (delta <= bpmin) {
                seg = 0;
            } else {
                int lo = 0, hi = 128;
                #pragma unroll
                for (int it = 0; it < 7; it++) {
                    const int mid = (lo + hi) >> 1;
                    if (sbp[mid] < delta) lo = mid + 1; else hi = mid;
                }
                seg = lo;
            }
            const bool valid = (nb != -1) && (ht < qt);
            const unsigned nbc = (nb == -1) ? 0u : (unsigned)nb;
            mtl[s] = nbc | ((unsigned)seg << 17) | ((unsigned)sg << 25)
                        | (valid ? (1u << 26) : 0u);
            dll[s] = delta;
            vll[s] = valid;
        }
    }

    const float4 zu = encode_task(lane, q4U, mtl[0], dll[0], vll[0],
                                  nemb4, A4, C4, semb4);
    ((float4*)g_z)[(unsigned)e * 32 + lane] = zu;

    const float4 zv = encode_task(lane, q4V, mtl[1], dll[1], vll[1],
                                  nemb4, A4, C4, semb4);
    ((float4*)g_z)[(unsigned)(NB + e) * 32 + lane] = zv;
}

// =========================================================================
// Kernel 3: split-bf16 mma.sync GEMM MLP. DOUBLE-BUFFERED 32-wide chunks
// (pitch 80B), 2 blocks/SM. Staging of chunk c+1 overlaps MMA of chunk c.
// FIXED: stageB now copies the full 32B per (row, half) via two cp16.
// =========================================================================
#define MMA_BF16(C, A, B0, B1) \
    asm volatile("mma.sync.aligned.m16n8k16.row.col.f32.bf16.bf16.f32 " \
        "{%0,%1,%2,%3}, {%4,%5,%6,%7}, {%8,%9}, {%0,%1,%2,%3};" \
        : "+f"((C)[0]), "+f"((C)[1]), "+f"((C)[2]), "+f"((C)[3]) \
        : "r"((A)[0]), "r"((A)[1]), "r"((A)[2]), "r"((A)[3]), "r"(B0), "r"(B1))

#define LDSM_X4(R, addr) \
    asm volatile("ldmatrix.sync.aligned.m8n8.x4.shared.b16 {%0,%1,%2,%3}, [%4];" \
        : "=r"((R)[0]), "=r"((R)[1]), "=r"((R)[2]), "=r"((R)[3]) : "r"(addr))

#define PITCH     80                 // 32 bf16 = 64B data + 16B pad (5x16B)
#define REGION_SZ (128 * PITCH)      // 10240
#define BUF_SZ    (4 * REGION_SZ)    // 40960: Ahi, Alo, Bhi, Blo
#define SMEM_TOT  (2 * BUF_SZ)       // 81920

extern __shared__ char dsm[];
__global__ void __launch_bounds__(256, 2) mlp_mma_kernel(
    const float* __restrict__ b1,
    const float* __restrict__ w2,
    const float* __restrict__ b2,
    float*       __restrict__ out)
{
    __shared__ float slog[128];

    const int tid  = threadIdx.x;
    const int wid  = tid >> 5;
    const int lane = tid & 31;
    const int e0   = blockIdx.x * 128;

    if (tid < 128) slog[tid] = 0.0f;

    const int wm = wid >> 1;
    const int wn = wid & 1;
    const int g  = lane >> 2;
    const int t2 = (lane & 3) * 2;

    const uint32_t uBase = (uint32_t)__cvta_generic_to_shared(dsm);
    const int lm = lane >> 3;
    const int lr = lane & 7;
    const uint32_t aofs = (uint32_t)(((lm & 1) * 8 + lr) * PITCH + (lm >> 1) * 16);
    const uint32_t bofs = (uint32_t)(((lm >> 1) * 8 + lr) * PITCH + (lm & 1) * 16);
    const uint32_t aRow0 = (uint32_t)((wm * 32) * PITCH);
    const uint32_t aRow1 = (uint32_t)((wm * 32 + 16) * PITCH);
    const uint32_t bBase = (uint32_t)((wn * 64) * PITCH);

    float acc[2][8][4];
    #pragma unroll
    for (int mt = 0; mt < 2; mt++)
        #pragma unroll
        for (int nt = 0; nt < 8; nt++)
            #pragma unroll
            for (int u = 0; u < 4; u++)
                acc[mt][nt][u] = 0.0f;

    const int f4 = tid & 7;          // float4 col 0..7 within 32-col chunk
    const int r0 = tid >> 3;         // row base 0..31
    const int bn = tid >> 1;         // B stage: n row
    const int bhk = tid & 1;         // B stage: 16-elem half

    // ---- staging helpers ----
    auto stageB = [&](int chunk, char* buf) {
        char* pBhi = buf + 2 * REGION_SZ;
        char* pBlo = buf + 3 * REGION_SZ;
        const int kk = chunk * 32 + bhk * 16;     // element index (bf16)
        const int so = bn * PITCH + bhk * 32;     // byte offset
        // 16 bf16 = 32 bytes -> two 16B copies
        cp16(pBhi + so,      &g_Whi[bn * 512 + kk]);
        cp16(pBhi + so + 16, &g_Whi[bn * 512 + kk + 8]);
        cp16(pBlo + so,      &g_Wlo[bn * 512 + kk]);
        cp16(pBlo + so + 16, &g_Wlo[bn * 512 + kk + 8]);
    };
    auto loadA = [&](int chunk, float4* fv) {
        const int region = chunk >> 2;
        const int cb4 = (chunk & 3) * 8;
        #pragma unroll
        for (int p = 0; p < 4; p++) {
            const int r = r0 + p * 32;
            float4 v;
            if (region == 0) {
                v = ((const float4*)g_z)[(unsigned)(e0 + r) * 32 + cb4 + f4];
            } else if (region == 1) {
                v = ((const float4*)g_z)[(unsigned)(NB + e0 + r) * 32 + cb4 + f4];
            } else {
                const float4 a = ((const float4*)g_z)[(unsigned)(e0 + r) * 32 + cb4 + f4];
                const float4 b = ((const float4*)g_z)[(unsigned)(NB + e0 + r) * 32 + cb4 + f4];
                if (region == 2) {
                    v.x = fabsf(a.x - b.x); v.y = fabsf(a.y - b.y);
                    v.z = fabsf(a.z - b.z); v.w = fabsf(a.w - b.w);
                } else {
                    v.x = a.x * b.x; v.y = a.y * b.y;
                    v.z = a.z * b.z; v.w = a.w * b.w;
                }
            }
            fv[p] = v;
        }
    };
    auto storeA = [&](char* buf, const float4* fv) {
        char* pAhi = buf;
        char* pAlo = buf + REGION_SZ;
        #pragma unroll
        for (int p = 0; p < 4; p++) {
            const int r = r0 + p * 32;
            const float4 v = fv[p];
            uint2 hv, lv;
            hv.x = cvt_bf16x2(v.x, v.y);
            hv.y = cvt_bf16x2(v.z, v.w);
            const float hxf = __uint_as_float(hv.x << 16);
            const float hyf = __uint_as_float(hv.x & 0xFFFF0000u);
            const float hzf = __uint_as_float(hv.y << 16);
            const float hwf = __uint_as_float(hv.y & 0xFFFF0000u);
            lv.x = cvt_bf16x2(v.x - hxf, v.y - hyf);
            lv.y = cvt_bf16x2(v.z - hzf, v.w - hwf);
            *(uint2*)(pAhi + r * PITCH + f4 * 8) = hv;
            *(uint2*)(pAlo + r * PITCH + f4 * 8) = lv;
        }
    };

    // ---- prologue: stage chunk 0 into buffer 0 ----
    {
        float4 fv[4];
        stageB(0, dsm);
        CP_COMMIT();
        loadA(0, fv);
        storeA(dsm, fv);
        CP_WAIT0();
    }
    __syncthreads();

    for (int chunk = 0; chunk < 16; chunk++) {
        char* bufN = dsm + ((chunk & 1) ^ 1) * BUF_SZ;
        const uint32_t uC = uBase + (uint32_t)((chunk & 1) * BUF_SZ);

        float4 fv[4];
        if (chunk < 15) {
            stageB(chunk + 1, bufN);    // async, no regs
            CP_COMMIT();
            loadA(chunk + 1, fv);       // LDGs in flight over MMA
        }

        // ---- MMA on current buffer ----
        const uint32_t uAhi = uC;
        const uint32_t uAlo = uC + REGION_SZ;
        const uint32_t uBhi = uC + 2 * REGION_SZ;
        const uint32_t uBlo = uC + 3 * REGION_SZ;
        #pragma unroll
        for (int ks = 0; ks < 2; ks++) {
            const uint32_t kof = (uint32_t)(ks * 32);
            uint32_t ah[2][4], al[2][4];
            LDSM_X4(ah[0], uAhi + aRow0 + aofs + kof);
            LDSM_X4(ah[1], uAhi + aRow1 + aofs + kof);
            LDSM_X4(al[0], uAlo + aRow0 + aofs + kof);
            LDSM_X4(al[1], uAlo + aRow1 + aofs + kof);

            uint32_t bh0[8], bh1[8], bl0[8], bl1[8];
            #pragma unroll
            for (int p = 0; p < 4; p++) {
                uint32_t rh[4], rl[4];
                LDSM_X4(rh, uBhi + bBase + (uint32_t)(p * 16 * PITCH) + bofs + kof);
                LDSM_X4(rl, uBlo + bBase + (uint32_t)(p * 16 * PITCH) + bofs + kof);
                bh0[2 * p] = rh[0]; bh1[2 * p] = rh[1];
                bh0[2 * p + 1] = rh[2]; bh1[2 * p + 1] = rh[3];
                bl0[2 * p] = rl[0]; bl1[2 * p] = rl[1];
                bl0[2 * p + 1] = rl[2]; bl1[2 * p + 1] = rl[3];
            }

            #pragma unroll
            for (int nt = 0; nt < 8; nt++) {
                #pragma unroll
                for (int mt = 0; mt < 2; mt++) {
                    MMA_BF16(acc[mt][nt], ah[mt], bh0[nt], bh1[nt]);
                    MMA_BF16(acc[mt][nt], ah[mt], bl0[nt], bl1[nt]);
                    MMA_BF16(acc[mt][nt], al[mt], bh0[nt], bh1[nt]);
                }
            }
        }

        if (chunk < 15) {
            storeA(bufN, fv);
            CP_WAIT0();
        }
        __syncthreads();
    }

    // ---- epilogue ----
    float b1v[16], w2v[16];
    #pragma unroll
    for (int nt = 0; nt < 8; nt++) {
        const int n = wn * 64 + nt * 8 + t2;
        b1v[nt * 2]     = __ldg(&b1[n]);
        b1v[nt * 2 + 1] = __ldg(&b1[n + 1]);
        w2v[nt * 2]     = __ldg(&w2[n]);
        w2v[nt * 2 + 1] = __ldg(&w2[n + 1]);
    }
    #pragma unroll
    for (int mt = 0; mt < 2; mt++) {
        float p1 = 0.0f, p2 = 0.0f;
        #pragma unroll
        for (int nt = 0; nt < 8; nt++) {
            p1 += fmaxf(acc[mt][nt][0] + b1v[2 * nt],     0.0f) * w2v[2 * nt]
                + fmaxf(acc[mt][nt][1] + b1v[2 * nt + 1], 0.0f) * w2v[2 * nt + 1];
            p2 += fmaxf(acc[mt][nt][2] + b1v[2 * nt],     0.0f) * w2v[2 * nt]
                + fmaxf(acc[mt][nt][3] + b1v[2 * nt + 1], 0.0f) * w2v[2 * nt + 1];
        }
        const int r1 = wm * 32 + mt * 16 + g;
        atomicAdd(&slog[r1], p1);
        atomicAdd(&slog[r1 + 8], p2);
    }
    __syncthreads();
    if (tid < 128) out[e0 + tid] = slog[tid] + b2[0];
}

// =========================================================================
extern "C" void kernel_launch(void* const* d_in, const int* in_sizes, int n_in,
                              void* d_out, int out_size)
{
    const int*   edge_index = (const int*)  d_in[0];
    const int*   ets        = (const int*)  d_in[1];
    const int*   hnb        = (const int*)  d_in[2];
    const int*   hts        = (const int*)  d_in[3];
    const int*   hsg        = (const int*)  d_in[4];
    const float* nemb       = (const float*)d_in[5];
    const float* semb       = (const float*)d_in[6];
    const float* tp_w1      = (const float*)d_in[7];
    const float* tp_b1      = (const float*)d_in[8];
    const float* tp_w2      = (const float*)d_in[9];
    const float* tp_b2      = (const float*)d_in[10];
    const float* em_w1      = (const float*)d_in[11];
    const float* em_b1      = (const float*)d_in[12];
    const float* em_w2      = (const float*)d_in[13];
    const float* em_b2      = (const float*)d_in[14];
    float* out = (float*)d_out;

    cudaFuncSetAttribute(mlp_mma_kernel,
                         cudaFuncAttributeMaxDynamicSharedMemorySize, SMEM_TOT);

    prolog_kernel<<<193, 512>>>(tp_w1, tp_b1, tp_w2, tp_b2, em_w1);
    encode_kernel<<<NB / 8, 256>>>(edge_index, ets, hnb, hts, hsg, nemb, semb);
    mlp_mma_kernel<<<NB / 128, 256, SMEM_TOT>>>(em_b1, em_w2, em_b2, out);
}